// round 1
// baseline (speedup 1.0000x reference)
#include <cuda_runtime.h>
#include <math.h>

#define BATCH 8
#define HW 1024
#define HS 512
#define NPIX (HS*HS)
#define NPTS 10
#define KP 512

// ---------------- scratch (device globals; no allocation) ----------------
__device__ float g_freq[BATCH*12*NPIX];      // 12-ch frequency stack at 512x512
__device__ float g_sal[BATCH*NPIX];          // saliency 512x512
__device__ float g_cand_val[BATCH*NPIX];     // peak candidates
__device__ int   g_cand_idx[BATCH*NPIX];
__device__ int   g_cand_cnt[BATCH];
__device__ float g_top_val[BATCH*KP];
__device__ int   g_top_idx[BATCH*KP];
__device__ int   g_top_cnt[BATCH];
__device__ int   g_rowflag[BATCH*HW];
__device__ int   g_colflag[BATCH*HW];

// ---------------- K0: zero counters/flags ----------------
__global__ void k0_zero(){
    int i = blockIdx.x*256 + threadIdx.x;
    if (i < BATCH) g_cand_cnt[i] = 0;
    if (i < BATCH*HW){ g_rowflag[i] = 0; g_colflag[i] = 0; }
}

// ---------------- K1: gray + Haar DWT + energy (freq ch 0..9) ----------------
__global__ void k1_freq(const float* __restrict__ rgb, const float* __restrict__ dep){
    int x = blockIdx.x*32 + threadIdx.x;
    int y = blockIdx.y*8  + threadIdx.y;
    int b = blockIdx.z;
    size_t plane = (size_t)HW*HW;
    const float* rp = rgb + (size_t)b*3*plane;
    const float* gp = rp + plane;
    const float* bp = gp + plane;
    const float* dp = dep + (size_t)b*plane;
    int i00 = (2*y)*HW + 2*x;
    int i01 = i00 + 1, i10 = i00 + HW, i11 = i00 + HW + 1;
    float v00 = (rp[i00]+gp[i00]+bp[i00])/3.0f;
    float v01 = (rp[i01]+gp[i01]+bp[i01])/3.0f;
    float v10 = (rp[i10]+gp[i10]+bp[i10])/3.0f;
    float v11 = (rp[i11]+gp[i11]+bp[i11])/3.0f;
    int p = y*HS + x;
    float* F = g_freq + (size_t)b*12*NPIX;
    {
        float a=v00*0.5f, c=v10*0.5f, e=v01*0.5f, f=v11*0.5f;
        float LL=a+c, LH=a-c, HL=e+f, HH=e-f;
        F[0*NPIX+p]=LL; F[1*NPIX+p]=LH; F[2*NPIX+p]=HL; F[3*NPIX+p]=HH;
        F[8*NPIX+p]=sqrtf(LH*LH+HL*HL+HH*HH+1e-8f);
    }
    {
        float a=dp[i00]*0.5f, c=dp[i10]*0.5f, e=dp[i01]*0.5f, f=dp[i11]*0.5f;
        float LL=a+c, LH=a-c, HL=e+f, HH=e-f;
        F[4*NPIX+p]=LL; F[5*NPIX+p]=LH; F[6*NPIX+p]=HL; F[7*NPIX+p]=HH;
        F[9*NPIX+p]=sqrtf(LH*LH+HL*HL+HH*HH+1e-8f);
    }
}

// ---------------- K2: 5x5 gaussian smooth of E channels (-> ch 10,11) ----------------
__global__ void k2_smooth(){
    __shared__ float gw[25];
    __shared__ float gs;
    int tid = threadIdx.y*32 + threadIdx.x;
    if (tid < 25){
        float fi = (float)(tid/5 - 2), fj = (float)(tid%5 - 2);
        gw[tid] = expf(-(fi*fi + fj*fj)*0.5f);
    }
    __syncthreads();
    if (tid == 0){ float s=0.f; for (int i=0;i<25;i++) s += gw[i]; gs = s; }
    __syncthreads();
    if (tid < 25) gw[tid] = gw[tid]/gs;
    __syncthreads();
    int x = blockIdx.x*32 + threadIdx.x;
    int y = blockIdx.y*8  + threadIdx.y;
    int b = blockIdx.z >> 1, e = blockIdx.z & 1;
    const float* src = g_freq + ((size_t)b*12 + 8 + e)*NPIX;
    float acc = 0.f;
    #pragma unroll
    for (int ky=-2; ky<=2; ky++){
        int yy = y + ky;
        if (yy < 0 || yy >= HS) continue;
        #pragma unroll
        for (int kx=-2; kx<=2; kx++){
            int xx = x + kx;
            if (xx < 0 || xx >= HS) continue;
            acc = fmaf(src[yy*HS+xx], gw[(ky+2)*5 + (kx+2)], acc);
        }
    }
    g_freq[((size_t)b*12 + 10 + e)*NPIX + y*HS + x] = acc;
}

// ---------------- K3: fused conv3x3(12->32) + BN + GELU + conv1x1 + sigmoid ----------------
__global__ __launch_bounds__(256) void k3_conv(
    const float* __restrict__ w1, const float* __restrict__ b1,
    const float* __restrict__ gam, const float* __restrict__ bet,
    const float* __restrict__ mu,  const float* __restrict__ var,
    const float* __restrict__ w2,  const float* __restrict__ b2)
{
    __shared__ float sIn[12*10*34];
    __shared__ __align__(16) float sW[3456];
    __shared__ float sSc[32], sSh[32], sW2[32];
    __shared__ float sB2;
    int tid = threadIdx.x;
    int b = blockIdx.z;
    int ty0 = blockIdx.y*8, tx0 = blockIdx.x*32;
    const float* F = g_freq + (size_t)b*12*NPIX;
    for (int l = tid; l < 12*340; l += 256){
        int c = l/340, r = l%340, iy = r/34, ix = r%34;
        int gy = ty0 + iy - 1, gx = tx0 + ix - 1;
        float v = 0.f;
        if (gy >= 0 && gy < HS && gx >= 0 && gx < HS) v = F[(size_t)c*NPIX + gy*HS + gx];
        sIn[l] = v;
    }
    for (int l = tid; l < 3456; l += 256){
        int tl = l >> 5, oc = l & 31;
        sW[l] = w1[oc*108 + tl];            // [c*9+tap][oc] layout
    }
    if (tid < 32){
        float inv = 1.0f/sqrtf(var[tid] + 1e-5f);
        float sc = gam[tid]*inv;
        sSc[tid] = sc;
        sSh[tid] = (b1[tid] - mu[tid])*sc + bet[tid];
        sW2[tid] = w2[tid];
    }
    if (tid == 0) sB2 = b2[0];
    __syncthreads();
    int ty = tid >> 5, tx = tid & 31;
    float acc[32];
    #pragma unroll
    for (int i=0;i<32;i++) acc[i] = 0.f;
    for (int c=0; c<12; c++){
        #pragma unroll
        for (int tap=0; tap<9; tap++){
            int ky = tap/3, kx = tap%3;
            float v = sIn[c*340 + (ty+ky)*34 + (tx+kx)];
            const float4* w4 = reinterpret_cast<const float4*>(&sW[(c*9+tap)*32]);
            #pragma unroll
            for (int q=0;q<8;q++){
                float4 ww = w4[q];
                acc[q*4+0] = fmaf(v, ww.x, acc[q*4+0]);
                acc[q*4+1] = fmaf(v, ww.y, acc[q*4+1]);
                acc[q*4+2] = fmaf(v, ww.z, acc[q*4+2]);
                acc[q*4+3] = fmaf(v, ww.w, acc[q*4+3]);
            }
        }
    }
    float z = sB2;
    #pragma unroll
    for (int oc=0; oc<32; oc++){
        float xv = fmaf(acc[oc], sSc[oc], sSh[oc]);
        float inner = 0.7978845608f*(xv + 0.044715f*xv*xv*xv);
        float gl = 0.5f*xv*(1.0f + tanhf(inner));
        z = fmaf(gl, sW2[oc], z);
    }
    float sal = 1.0f/(1.0f + expf(-z));
    g_sal[(size_t)b*NPIX + (ty0+ty)*HS + (tx0+tx)] = sal;
}

// ---------------- K4: bilinear x2 upsample -> masks + row/col occupancy ----------------
__global__ void k4_resize(float* __restrict__ masks){
    __shared__ int colAny[32];
    int tx = threadIdx.x, ty = threadIdx.y;
    if (ty == 0) colAny[tx] = 0;
    __syncthreads();
    int X = blockIdx.x*32 + tx;
    int Y = blockIdx.y*8  + ty;
    int b = blockIdx.z;
    const float* s = g_sal + (size_t)b*NPIX;
    float fx = X*0.5f - 0.25f, fy = Y*0.5f - 0.25f;
    int x0 = (int)floorf(fx), y0 = (int)floorf(fy);
    float wx = fx - (float)x0, wy = fy - (float)y0;
    int x1 = min(x0+1, HS-1), y1 = min(y0+1, HS-1);
    x0 = max(x0, 0); y0 = max(y0, 0);
    float v00=s[y0*HS+x0], v01=s[y0*HS+x1], v10=s[y1*HS+x0], v11=s[y1*HS+x1];
    float v = (1.f-wy)*((1.f-wx)*v00 + wx*v01) + wy*((1.f-wx)*v10 + wx*v11);
    masks[(size_t)b*HW*HW + (size_t)Y*HW + X] = v;
    bool on = v > 0.5f;
    unsigned m = __ballot_sync(0xffffffffu, on);
    if (tx == 0 && m) atomicOr(&g_rowflag[b*HW + Y], 1);
    if (on) colAny[tx] = 1;
    __syncthreads();
    if (ty == 0 && colAny[tx]) atomicOr(&g_colflag[b*HW + X], 1);
}

// ---------------- K5: 3x3 local-max peak detection (warp-aggregated append) ----------------
__global__ void k5_peaks(){
    int x = blockIdx.x*32 + threadIdx.x;
    int y = blockIdx.y*8  + threadIdx.y;
    int b = blockIdx.z;
    const float* s = g_sal + (size_t)b*NPIX;
    float v = s[y*HS + x];
    float mp = v;
    #pragma unroll
    for (int dy=-1; dy<=1; dy++){
        int yy = y + dy; if (yy < 0 || yy >= HS) continue;
        #pragma unroll
        for (int dx=-1; dx<=1; dx++){
            int xx = x + dx; if (xx < 0 || xx >= HS) continue;
            mp = fmaxf(mp, s[yy*HS + xx]);
        }
    }
    bool pk = (v == mp) && (v > 0.f);
    unsigned m = __ballot_sync(0xffffffffu, pk);
    if (m){
        int lane = threadIdx.x;
        int leader = __ffs(m) - 1;
        int base = 0;
        if (lane == leader) base = atomicAdd(&g_cand_cnt[b], __popc(m));
        base = __shfl_sync(0xffffffffu, base, leader);
        if (pk){
            int r = __popc(m & ((1u << lane) - 1u));
            g_cand_val[(size_t)b*NPIX + base + r] = v;
            g_cand_idx[(size_t)b*NPIX + base + r] = y*HS + x;
        }
    }
}

// ---------------- K6: histogram-select + bitonic -> sorted top-512 ----------------
__global__ __launch_bounds__(1024) void k6_select(){
    extern __shared__ unsigned char sraw[];
    unsigned long long* keys = (unsigned long long*)sraw;               // 8192 u64
    unsigned int* hist = (unsigned int*)(sraw + 8192*sizeof(unsigned long long)); // 4096 u32
    __shared__ int sT;
    __shared__ int sM;
    int b = blockIdx.x, tid = threadIdx.x;
    int N = g_cand_cnt[b];
    if (N > NPIX) N = NPIX;
    for (int i = tid; i < 4096; i += 1024) hist[i] = 0u;
    if (tid == 0) sM = 0;
    __syncthreads();
    const float* cv = g_cand_val + (size_t)b*NPIX;
    const int*   ci = g_cand_idx + (size_t)b*NPIX;
    for (int i = tid; i < N; i += 1024){
        float v = cv[i];
        int bin = (int)(v*4096.0f);
        bin = max(0, min(4095, bin));
        atomicAdd(&hist[bin], 1u);
    }
    __syncthreads();
    if (tid == 0){
        int need = min(KP, N);
        int acc = 0, t = 4095;
        for (; t > 0; t--){ acc += (int)hist[t]; if (acc >= need) break; }
        sT = t;
    }
    __syncthreads();
    int T = sT;
    for (int i = tid; i < N; i += 1024){
        float v = cv[i];
        int bin = (int)(v*4096.0f);
        bin = max(0, min(4095, bin));
        if (bin >= T){
            int p = atomicAdd(&sM, 1);
            if (p < 8192){
                keys[p] = ((unsigned long long)__float_as_uint(v) << 32)
                        | (unsigned int)(~(unsigned)ci[i]);   // val desc, idx asc
            }
        }
    }
    __syncthreads();
    int M = min(sM, 8192);
    for (int i = M + tid; i < 8192; i += 1024) keys[i] = 0ULL;
    __syncthreads();
    // bitonic ascending; top entries end at the back
    for (int k = 2; k <= 8192; k <<= 1){
        for (int j = k >> 1; j > 0; j >>= 1){
            for (int i = tid; i < 8192; i += 1024){
                int ixj = i ^ j;
                if (ixj > i){
                    unsigned long long a = keys[i], c = keys[ixj];
                    bool up = ((i & k) == 0);
                    if ((a > c) == up){ keys[i] = c; keys[ixj] = a; }
                }
            }
            __syncthreads();
        }
    }
    if (tid < KP){
        unsigned long long kk = keys[8191 - tid];
        g_top_val[b*KP + tid] = __uint_as_float((unsigned)(kk >> 32));
        g_top_idx[b*KP + tid] = (int)(~(unsigned)(kk & 0xffffffffu));
    }
    if (tid == 0) g_top_cnt[b] = min(N, KP);
}

// ---------------- K7: fallback top-10 (non-peaks) + greedy NMS + coords/labels ----------------
__global__ __launch_bounds__(256) void k7_points(float* __restrict__ out){
    __shared__ int s_ti[KP];
    __shared__ unsigned char s_avail[KP];
    __shared__ float fbv[256*NPTS];
    __shared__ int   fbi[256*NPTS];
    int b = blockIdx.x, tid = threadIdx.x;
    for (int i = tid; i < KP; i += 256){ s_ti[i] = g_top_idx[b*KP + i]; s_avail[i] = 1; }
    const float* s = g_sal + (size_t)b*NPIX;
    float lv[NPTS]; int li[NPTS];
    #pragma unroll
    for (int k=0;k<NPTS;k++){ lv[k] = -1e30f; li[k] = 0x7fffffff; }
    for (int p = tid; p < NPIX; p += 256){
        float v = s[p];
        if (v <= lv[NPTS-1]) continue;
        int y = p >> 9, x = p & (HS-1);
        float mp = v;
        for (int dy=-1; dy<=1; dy++){
            int yy = y + dy; if (yy < 0 || yy >= HS) continue;
            for (int dx=-1; dx<=1; dx++){
                int xx = x + dx; if (xx < 0 || xx >= HS) continue;
                mp = fmaxf(mp, s[yy*HS + xx]);
            }
        }
        if (v == mp) continue;   // peaks excluded from fallback
        int pos = NPTS-1;
        while (pos > 0 && v > lv[pos-1]) pos--;
        for (int q = NPTS-1; q > pos; q--){ lv[q]=lv[q-1]; li[q]=li[q-1]; }
        lv[pos] = v; li[pos] = p;
    }
    #pragma unroll
    for (int k=0;k<NPTS;k++){ fbv[tid*NPTS+k]=lv[k]; fbi[tid*NPTS+k]=li[k]; }
    __syncthreads();
    if (tid == 0){
        float fv[NPTS]; int fi[NPTS];
        for (int k=0;k<NPTS;k++){ fv[k] = -1e30f; fi[k] = 0x7fffffff; }
        for (int t=0; t<256*NPTS; t++){
            float v = fbv[t]; int ix = fbi[t];
            if (v < fv[NPTS-1] || (v == fv[NPTS-1] && ix >= fi[NPTS-1])) continue;
            int pos = NPTS-1;
            while (pos > 0 && (v > fv[pos-1] || (v == fv[pos-1] && ix < fi[pos-1]))) pos--;
            for (int q = NPTS-1; q > pos; q--){ fv[q]=fv[q-1]; fi[q]=fi[q-1]; }
            fv[pos] = v; fi[pos] = ix;
        }
        // greedy NMS: min_dist = 25 -> suppress d^2 < 625
        int Kv = g_top_cnt[b];
        int chosen[NPTS]; int cnt = 0;
        for (int i = 0; i < Kv && cnt < NPTS; i++){
            if (!s_avail[i]) continue;
            int idx = s_ti[i];
            chosen[cnt++] = idx;
            int xi = idx & (HS-1), yi = idx >> 9;
            for (int j = i+1; j < Kv; j++){
                if (!s_avail[j]) continue;
                int dx = (s_ti[j] & (HS-1)) - xi;
                int dy = (s_ti[j] >> 9) - yi;
                if (dx*dx + dy*dy < 625) s_avail[j] = 0;
            }
        }
        for (int slot = 0; slot < NPTS; slot++){
            int si = (slot < cnt) ? chosen[slot] : fi[slot - cnt];
            float cx = (float)(si & (HS-1)) * (1.0f/512.0f);
            float cy = (float)(si >> 9)     * (1.0f/512.0f);
            out[b*20 + slot*2 + 0] = cx;
            out[b*20 + slot*2 + 1] = cy;
            out[BATCH*NPTS*2 + b*NPTS + slot] = 1.0f;   // labels
        }
    }
}

// ---------------- K8: boxes from row/col flags ----------------
__global__ void k8_boxes(float* __restrict__ out){
    int b = threadIdx.x;
    if (b >= BATCH) return;
    int rmin = HW, rmax = -1, cmin = HW, cmax = -1;
    for (int i = 0; i < HW; i++){
        if (g_rowflag[b*HW + i]){ if (i < rmin) rmin = i; rmax = i; }
        if (g_colflag[b*HW + i]){ if (i < cmin) cmin = i; cmax = i; }
    }
    float* bx = out + BATCH*NPTS*2 + BATCH*NPTS + b*4;
    if (rmax >= 0){ bx[0]=(float)cmin; bx[1]=(float)rmin; bx[2]=(float)cmax; bx[3]=(float)rmax; }
    else          { bx[0]=0.f; bx[1]=0.f; bx[2]=(float)(HW-1); bx[3]=(float)(HW-1); }
}

// ---------------- launch ----------------
extern "C" void kernel_launch(void* const* d_in, const int* in_sizes, int n_in,
                              void* d_out, int out_size){
    (void)in_sizes; (void)n_in; (void)out_size;
    const float* rgb = (const float*)d_in[0];
    const float* dep = (const float*)d_in[1];
    const float* w1  = (const float*)d_in[2];
    const float* b1  = (const float*)d_in[3];
    const float* gam = (const float*)d_in[4];
    const float* bet = (const float*)d_in[5];
    const float* mu  = (const float*)d_in[6];
    const float* var = (const float*)d_in[7];
    const float* w2  = (const float*)d_in[8];
    const float* b2  = (const float*)d_in[9];
    float* out = (float*)d_out;
    float* masks = out + (BATCH*NPTS*2 + BATCH*NPTS + BATCH*4);  // 272

    dim3 blk(32,8);
    k0_zero<<<(BATCH*HW + 255)/256, 256>>>();
    k1_freq<<<dim3(16,64,BATCH), blk>>>(rgb, dep);
    k2_smooth<<<dim3(16,64,BATCH*2), blk>>>();
    k3_conv<<<dim3(16,64,BATCH), 256>>>(w1,b1,gam,bet,mu,var,w2,b2);
    k4_resize<<<dim3(32,128,BATCH), blk>>>(masks);
    k5_peaks<<<dim3(16,64,BATCH), blk>>>();
    cudaFuncSetAttribute(k6_select, cudaFuncAttributeMaxDynamicSharedMemorySize, 81920);
    k6_select<<<BATCH, 1024, 81920>>>();
    k7_points<<<BATCH, 256>>>(out);
    k8_boxes<<<1, 32>>>(out);
}

// round 3
// speedup vs baseline: 1.5283x; 1.5283x over previous
#include <cuda_runtime.h>
#include <math.h>

#define BATCH 8
#define HW 1024
#define HS 512
#define NPIX (HS*HS)
#define NPTS 10
#define KP 512
#define SORTN 8192

// ---------------- scratch (device globals; no allocation) ----------------
__device__ float g_freq[BATCH*12*NPIX];      // 12-ch frequency stack at 512x512
__device__ float g_sal[BATCH*NPIX];          // saliency 512x512
__device__ float g_cand_val[BATCH*NPIX];     // peak candidates
__device__ int   g_cand_idx[BATCH*NPIX];
__device__ int   g_cand_cnt[BATCH];
__device__ int   g_rowflag[BATCH*HW];
__device__ int   g_colflag[BATCH*HW];

// ---------------- packed f32x2 helpers ----------------
__device__ __forceinline__ unsigned long long fma2(unsigned long long a,
                                                   unsigned long long b,
                                                   unsigned long long c){
    unsigned long long d;
    asm("fma.rn.f32x2 %0, %1, %2, %3;" : "=l"(d) : "l"(a), "l"(b), "l"(c));
    return d;
}
__device__ __forceinline__ unsigned long long pack2(float v){
    unsigned long long d;
    asm("mov.b64 %0, {%1, %1};" : "=l"(d) : "f"(v));
    return d;
}
__device__ __forceinline__ void unpack2(unsigned long long p, float& lo, float& hi){
    asm("mov.b64 {%0, %1}, %2;" : "=f"(lo), "=f"(hi) : "l"(p));
}

// ---------------- K0: zero counters/flags ----------------
__global__ void k0_zero(){
    int i = blockIdx.x*256 + threadIdx.x;
    if (i < BATCH) g_cand_cnt[i] = 0;
    if (i < BATCH*HW){ g_rowflag[i] = 0; g_colflag[i] = 0; }
}

// ---------------- K1: gray + Haar DWT + energy (freq ch 0..9) ----------------
__global__ void k1_freq(const float* __restrict__ rgb, const float* __restrict__ dep){
    int x = blockIdx.x*32 + threadIdx.x;
    int y = blockIdx.y*8  + threadIdx.y;
    int b = blockIdx.z;
    size_t plane = (size_t)HW*HW;
    const float2* rp = (const float2*)(rgb + (size_t)b*3*plane);
    const float2* gp = rp + plane/2;
    const float2* bp = gp + plane/2;
    const float2* dp = (const float2*)(dep + (size_t)b*plane);
    int r0 = y*HW + x;          // float2 index of row 2y, col pair x
    int r1 = r0 + HW/2;
    float2 ra = rp[r0], rb = rp[r1], ga = gp[r0], gb = gp[r1], ba = bp[r0], bb = bp[r1];
    float v00 = (ra.x+ga.x+ba.x)/3.0f;
    float v01 = (ra.y+ga.y+ba.y)/3.0f;
    float v10 = (rb.x+gb.x+bb.x)/3.0f;
    float v11 = (rb.y+gb.y+bb.y)/3.0f;
    int p = y*HS + x;
    float* F = g_freq + (size_t)b*12*NPIX;
    {
        float a=v00*0.5f, c=v10*0.5f, e=v01*0.5f, f=v11*0.5f;
        float LL=a+c, LH=a-c, HL=e+f, HH=e-f;
        F[0*NPIX+p]=LL; F[1*NPIX+p]=LH; F[2*NPIX+p]=HL; F[3*NPIX+p]=HH;
        F[8*NPIX+p]=sqrtf(LH*LH+HL*HL+HH*HH+1e-8f);
    }
    {
        float2 da = dp[r0], db = dp[r1];
        float a=da.x*0.5f, c=db.x*0.5f, e=da.y*0.5f, f=db.y*0.5f;
        float LL=a+c, LH=a-c, HL=e+f, HH=e-f;
        F[4*NPIX+p]=LL; F[5*NPIX+p]=LH; F[6*NPIX+p]=HL; F[7*NPIX+p]=HH;
        F[9*NPIX+p]=sqrtf(LH*LH+HL*HL+HH*HH+1e-8f);
    }
}

// ---------------- K2: 5x5 gaussian smooth of E channels (-> ch 10,11) ----------------
__global__ void k2_smooth(){
    __shared__ float gw[25];
    __shared__ float gs;
    int tid = threadIdx.y*32 + threadIdx.x;
    if (tid < 25){
        float fi = (float)(tid/5 - 2), fj = (float)(tid%5 - 2);
        gw[tid] = expf(-(fi*fi + fj*fj)*0.5f);
    }
    __syncthreads();
    if (tid == 0){ float s=0.f; for (int i=0;i<25;i++) s += gw[i]; gs = s; }
    __syncthreads();
    if (tid < 25) gw[tid] = gw[tid]/gs;
    __syncthreads();
    int x = blockIdx.x*32 + threadIdx.x;
    int y = blockIdx.y*8  + threadIdx.y;
    int b = blockIdx.z >> 1, e = blockIdx.z & 1;
    const float* src = g_freq + ((size_t)b*12 + 8 + e)*NPIX;
    float acc = 0.f;
    #pragma unroll
    for (int ky=-2; ky<=2; ky++){
        int yy = y + ky;
        if (yy < 0 || yy >= HS) continue;
        #pragma unroll
        for (int kx=-2; kx<=2; kx++){
            int xx = x + kx;
            if (xx < 0 || xx >= HS) continue;
            acc = fmaf(src[yy*HS+xx], gw[(ky+2)*5 + (kx+2)], acc);
        }
    }
    g_freq[((size_t)b*12 + 10 + e)*NPIX + y*HS + x] = acc;
}

// ---------------- K3: fused conv3x3(12->32)+BN+GELU+conv1x1+sigmoid, f32x2 packed ----------------
__global__ __launch_bounds__(256) void k3_conv(
    const float* __restrict__ w1, const float* __restrict__ b1,
    const float* __restrict__ gam, const float* __restrict__ bet,
    const float* __restrict__ mu,  const float* __restrict__ var,
    const float* __restrict__ w2,  const float* __restrict__ b2)
{
    __shared__ float sIn[12*10*34];
    __shared__ __align__(16) float sW[3456];
    __shared__ float sSc[32], sSh[32], sW2[32];
    __shared__ float sB2;
    int tid = threadIdx.x;
    int b = blockIdx.z;
    int ty0 = blockIdx.y*8, tx0 = blockIdx.x*32;
    const float* F = g_freq + (size_t)b*12*NPIX;
    for (int l = tid; l < 12*340; l += 256){
        int c = l/340, r = l%340, iy = r/34, ix = r%34;
        int gy = ty0 + iy - 1, gx = tx0 + ix - 1;
        float v = 0.f;
        if (gy >= 0 && gy < HS && gx >= 0 && gx < HS) v = F[(size_t)c*NPIX + gy*HS + gx];
        sIn[l] = v;
    }
    for (int l = tid; l < 3456; l += 256){
        int tl = l >> 5, oc = l & 31;
        sW[l] = w1[oc*108 + tl];            // sW[(c*9+tap)*32 + oc]
    }
    if (tid < 32){
        float inv = 1.0f/sqrtf(var[tid] + 1e-5f);
        float sc = gam[tid]*inv;
        sSc[tid] = sc;
        sSh[tid] = (b1[tid] - mu[tid])*sc + bet[tid];
        sW2[tid] = w2[tid];
    }
    if (tid == 0) sB2 = b2[0];
    __syncthreads();
    int ty = tid >> 5, tx = tid & 31;
    unsigned long long acc2[16];   // acc2[j] accumulates output channels {2j, 2j+1}
    #pragma unroll
    for (int i=0;i<16;i++) acc2[i] = 0ULL;
    const ulonglong2* sWu = reinterpret_cast<const ulonglong2*>(sW);
    for (int c=0; c<12; c++){
        #pragma unroll
        for (int tap=0; tap<9; tap++){
            int ky = tap/3, kx = tap%3;
            float v = sIn[c*340 + (ty+ky)*34 + (tx+kx)];
            unsigned long long vv = pack2(v);
            const ulonglong2* wrow = sWu + (c*9+tap)*8;
            #pragma unroll
            for (int q=0;q<8;q++){
                ulonglong2 wp = wrow[q];            // wp.x = oc{4q,4q+1}, wp.y = oc{4q+2,4q+3}
                acc2[2*q+0] = fma2(vv, wp.x, acc2[2*q+0]);
                acc2[2*q+1] = fma2(vv, wp.y, acc2[2*q+1]);
            }
        }
    }
    float z = sB2;
    #pragma unroll
    for (int j=0; j<16; j++){
        float a0, a1;
        unpack2(acc2[j], a0, a1);
        int oc = 2*j;
        {
            float xv = fmaf(a0, sSc[oc], sSh[oc]);
            float inner = 0.7978845608f*(xv + 0.044715f*xv*xv*xv);
            float gl = 0.5f*xv*(1.0f + tanhf(inner));
            z = fmaf(gl, sW2[oc], z);
        }
        {
            float xv = fmaf(a1, sSc[oc+1], sSh[oc+1]);
            float inner = 0.7978845608f*(xv + 0.044715f*xv*xv*xv);
            float gl = 0.5f*xv*(1.0f + tanhf(inner));
            z = fmaf(gl, sW2[oc+1], z);
        }
    }
    float sal = 1.0f/(1.0f + expf(-z));
    g_sal[(size_t)b*NPIX + (ty0+ty)*HS + (tx0+tx)] = sal;
}

// ---------------- K4: bilinear x2 upsample -> masks + row/col occupancy ----------------
__global__ void k4_resize(float* __restrict__ masks){
    __shared__ int colAny[32];
    int tx = threadIdx.x, ty = threadIdx.y;
    if (ty == 0) colAny[tx] = 0;
    __syncthreads();
    int X = blockIdx.x*32 + tx;
    int Y = blockIdx.y*8  + ty;
    int b = blockIdx.z;
    const float* s = g_sal + (size_t)b*NPIX;
    float fx = X*0.5f - 0.25f, fy = Y*0.5f - 0.25f;
    int x0 = (int)floorf(fx), y0 = (int)floorf(fy);
    float wx = fx - (float)x0, wy = fy - (float)y0;
    int x1 = min(x0+1, HS-1), y1 = min(y0+1, HS-1);
    x0 = max(x0, 0); y0 = max(y0, 0);
    float v00=s[y0*HS+x0], v01=s[y0*HS+x1], v10=s[y1*HS+x0], v11=s[y1*HS+x1];
    float v = (1.f-wy)*((1.f-wx)*v00 + wx*v01) + wy*((1.f-wx)*v10 + wx*v11);
    masks[(size_t)b*HW*HW + (size_t)Y*HW + X] = v;
    bool on = v > 0.5f;
    unsigned m = __ballot_sync(0xffffffffu, on);
    if (tx == 0 && m) atomicOr(&g_rowflag[b*HW + Y], 1);
    if (on) colAny[tx] = 1;
    __syncthreads();
    if (ty == 0 && colAny[tx]) atomicOr(&g_colflag[b*HW + X], 1);
}

// ---------------- K5: 3x3 local-max peak detection (warp-aggregated append) ----------------
__global__ void k5_peaks(){
    int x = blockIdx.x*32 + threadIdx.x;
    int y = blockIdx.y*8  + threadIdx.y;
    int b = blockIdx.z;
    const float* s = g_sal + (size_t)b*NPIX;
    float v = s[y*HS + x];
    float mp = v;
    #pragma unroll
    for (int dy=-1; dy<=1; dy++){
        int yy = y + dy; if (yy < 0 || yy >= HS) continue;
        #pragma unroll
        for (int dx=-1; dx<=1; dx++){
            int xx = x + dx; if (xx < 0 || xx >= HS) continue;
            mp = fmaxf(mp, s[yy*HS + xx]);
        }
    }
    bool pk = (v == mp) && (v > 0.f);
    unsigned m = __ballot_sync(0xffffffffu, pk);
    if (m){
        int lane = threadIdx.x;
        int leader = __ffs(m) - 1;
        int base = 0;
        if (lane == leader) base = atomicAdd(&g_cand_cnt[b], __popc(m));
        base = __shfl_sync(0xffffffffu, base, leader);
        if (pk){
            int r = __popc(m & ((1u << lane) - 1u));
            g_cand_val[(size_t)b*NPIX + base + r] = v;
            g_cand_idx[(size_t)b*NPIX + base + r] = y*HS + x;
        }
    }
}

// ---------------- K6: select top-512 + greedy NMS + fallback top-10 + coords ----------------
// smem layout (dynamic, 86528 B):
//   [0, 65536)        u64 keys[8192]
//   [65536, 81920)    u32 hist[4096]      (reused as u64 bestkey[1024] after hist phase)
//   [81920, 86016)    int part[1024]
//   [86016, 86528)    u8  avail[512]
__global__ __launch_bounds__(1024) void k6_points(float* __restrict__ out){
    extern __shared__ unsigned char sraw[];
    unsigned long long* keys = (unsigned long long*)sraw;
    unsigned int* hist = (unsigned int*)(sraw + 65536);
    unsigned long long* bestkey = (unsigned long long*)(sraw + 65536); // alias after hist done
    int* part = (int*)(sraw + 81920);
    unsigned char* avail = (unsigned char*)(sraw + 86016);
    __shared__ int sT, sM, sCnt;
    __shared__ int chosenIdx[NPTS];
    __shared__ int fbIdx[NPTS];
    __shared__ unsigned long long sWin;

    int b = blockIdx.x, tid = threadIdx.x;
    int N = g_cand_cnt[b];
    if (N > NPIX) N = NPIX;
    int need = min(KP, N);

    // histogram
    hist[tid] = 0u; hist[tid+1024] = 0u; hist[tid+2048] = 0u; hist[tid+3072] = 0u;
    if (tid == 0){ sT = 0; sM = 0; }
    __syncthreads();
    const float* cv = g_cand_val + (size_t)b*NPIX;
    const int*   ci = g_cand_idx + (size_t)b*NPIX;
    for (int i = tid; i < N; i += 1024){
        int bin = max(0, min(4095, (int)(cv[i]*4096.0f)));
        atomicAdd(&hist[bin], 1u);
    }
    __syncthreads();
    // per-thread group of 4 bins, then parallel suffix scan of partials
    int t4 = tid*4;
    int h0 = hist[t4], h1 = hist[t4+1], h2 = hist[t4+2], h3 = hist[t4+3];
    part[tid] = h0+h1+h2+h3;
    __syncthreads();
    for (int d = 1; d < 1024; d <<= 1){
        int v = (tid + d < 1024) ? part[tid + d] : 0;
        __syncthreads();
        part[tid] += v;
        __syncthreads();
    }
    {
        int base = part[tid];              // suffix at bin t4
        int s1 = base - h0, s2 = s1 - h1, s3 = s2 - h2;
        int bestT = -1;
        if (s3 >= need) bestT = t4+3;
        else if (s2 >= need) bestT = t4+2;
        else if (s1 >= need) bestT = t4+1;
        else if (base >= need) bestT = t4;
        if (bestT >= 0) atomicMax(&sT, bestT);
    }
    __syncthreads();
    int T = sT;
    // compact survivors
    for (int i = tid; i < N; i += 1024){
        float v = cv[i];
        int bin = max(0, min(4095, (int)(v*4096.0f)));
        if (bin >= T){
            int p = atomicAdd(&sM, 1);
            if (p < SORTN)
                keys[p] = ((unsigned long long)__float_as_uint(v) << 32)
                        | (unsigned int)(~(unsigned)ci[i]);
        }
    }
    __syncthreads();
    int M = min(sM, SORTN);
    for (int i = M + tid; i < SORTN; i += 1024) keys[i] = 0ULL;
    __syncthreads();
    // bitonic ascending (top at the back)
    for (int k = 2; k <= SORTN; k <<= 1){
        for (int j = k >> 1; j > 0; j >>= 1){
            #pragma unroll
            for (int r = 0; r < SORTN/1024; r++){
                int i = r*1024 + tid;
                int ixj = i ^ j;
                if (ixj > i){
                    unsigned long long a = keys[i], c = keys[ixj];
                    bool up = ((i & k) == 0);
                    if ((a > c) == up){ keys[i] = c; keys[ixj] = a; }
                }
            }
            __syncthreads();
        }
    }
    if (tid < KP) avail[tid] = 1;
    __syncthreads();

    // ---- fallback: per-thread register top-10 over non-peak pixels ----
    const float* s = g_sal + (size_t)b*NPIX;
    float lv[NPTS]; int li[NPTS];
    #pragma unroll
    for (int k=0;k<NPTS;k++){ lv[k] = -1e30f; li[k] = 0x7fffffff; }
    for (int p = tid; p < NPIX; p += 1024){
        float v = s[p];
        if (v <= lv[NPTS-1]) continue;
        int y = p >> 9, x = p & (HS-1);
        float mp = v;
        #pragma unroll
        for (int dy=-1; dy<=1; dy++){
            int yy = y + dy; if (yy < 0 || yy >= HS) continue;
            #pragma unroll
            for (int dx=-1; dx<=1; dx++){
                int xx = x + dx; if (xx < 0 || xx >= HS) continue;
                mp = fmaxf(mp, s[yy*HS + xx]);
            }
        }
        if (v == mp) continue;   // peaks excluded from fallback
        float cvv = v; int cix = p;
        #pragma unroll
        for (int k=0;k<NPTS;k++){
            bool better = (cvv > lv[k]) || (cvv == lv[k] && cix < li[k]);
            float tv = lv[k]; int ti = li[k];
            if (better){ lv[k] = cvv; li[k] = cix; cvv = tv; cix = ti; }
        }
    }
    // 10 rounds of block argmax to merge the 1024 register lists
    int ptr = 0;
    for (int r = 0; r < NPTS; r++){
        unsigned long long mykey = 0ULL;
        if (ptr < NPTS && lv[ptr] > -1e29f)
            mykey = ((unsigned long long)__float_as_uint(lv[ptr]) << 32)
                  | (unsigned int)(~(unsigned)li[ptr]);
        bestkey[tid] = mykey;
        __syncthreads();
        for (int st = 512; st > 0; st >>= 1){
            if (tid < st){
                unsigned long long o = bestkey[tid+st];
                if (o > bestkey[tid]) bestkey[tid] = o;
            }
            __syncthreads();
        }
        unsigned long long win = bestkey[0];
        if (tid == 0){ fbIdx[r] = (int)(~(unsigned)(win & 0xffffffffu)); sWin = win; }
        __syncthreads();
        if (mykey != 0ULL && mykey == sWin) ptr++;
        __syncthreads();
    }

    // ---- greedy NMS on sorted top-512 (serial, small) ----
    if (tid == 0){
        int Kv = min(N, KP);
        int cnt = 0;
        for (int i = 0; i < Kv && cnt < NPTS; i++){
            if (!avail[i]) continue;
            int idx = (int)(~(unsigned)(keys[SORTN-1-i] & 0xffffffffu));
            chosenIdx[cnt++] = idx;
            int xi = idx & (HS-1), yi = idx >> 9;
            for (int j = i+1; j < Kv; j++){
                if (!avail[j]) continue;
                int oj = (int)(~(unsigned)(keys[SORTN-1-j] & 0xffffffffu));
                int dx = (oj & (HS-1)) - xi;
                int dy = (oj >> 9) - yi;
                if (dx*dx + dy*dy < 625) avail[j] = 0;
            }
        }
        sCnt = cnt;
    }
    __syncthreads();
    if (tid < NPTS){
        int cnt = sCnt;
        int si = (tid < cnt) ? chosenIdx[tid] : fbIdx[tid - cnt];
        out[b*20 + tid*2 + 0] = (float)(si & (HS-1)) * (1.0f/512.0f);
        out[b*20 + tid*2 + 1] = (float)(si >> 9)     * (1.0f/512.0f);
        out[BATCH*NPTS*2 + b*NPTS + tid] = 1.0f;     // labels
    }
}

// ---------------- K8: boxes from row/col flags (parallel reductions) ----------------
__global__ __launch_bounds__(1024) void k8_boxes(float* __restrict__ out){
    __shared__ int sred[1024];
    int b = blockIdx.x, tid = threadIdx.x;
    int rf = g_rowflag[b*HW + tid];
    int cf = g_colflag[b*HW + tid];
    int res[4];
    // 0: rmin, 1: rmax, 2: cmin, 3: cmax
    int init[4] = { rf ? tid : HW, rf ? tid : -1, cf ? tid : HW, cf ? tid : -1 };
    #pragma unroll
    for (int w = 0; w < 4; w++){
        sred[tid] = init[w];
        __syncthreads();
        for (int st = 512; st > 0; st >>= 1){
            if (tid < st){
                int o = sred[tid+st];
                sred[tid] = (w == 0 || w == 2) ? min(sred[tid], o) : max(sred[tid], o);
            }
            __syncthreads();
        }
        res[w] = sred[0];
        __syncthreads();
    }
    if (tid == 0){
        float* bx = out + BATCH*NPTS*2 + BATCH*NPTS + b*4;
        if (res[1] >= 0){ bx[0]=(float)res[2]; bx[1]=(float)res[0]; bx[2]=(float)res[3]; bx[3]=(float)res[1]; }
        else            { bx[0]=0.f; bx[1]=0.f; bx[2]=(float)(HW-1); bx[3]=(float)(HW-1); }
    }
}

// ---------------- launch ----------------
extern "C" void kernel_launch(void* const* d_in, const int* in_sizes, int n_in,
                              void* d_out, int out_size){
    (void)in_sizes; (void)n_in; (void)out_size;
    const float* rgb = (const float*)d_in[0];
    const float* dep = (const float*)d_in[1];
    const float* w1  = (const float*)d_in[2];
    const float* b1  = (const float*)d_in[3];
    const float* gam = (const float*)d_in[4];
    const float* bet = (const float*)d_in[5];
    const float* mu  = (const float*)d_in[6];
    const float* var = (const float*)d_in[7];
    const float* w2  = (const float*)d_in[8];
    const float* b2  = (const float*)d_in[9];
    float* out = (float*)d_out;
    float* masks = out + (BATCH*NPTS*2 + BATCH*NPTS + BATCH*4);  // 272

    dim3 blk(32,8);
    k0_zero<<<(BATCH*HW + 255)/256, 256>>>();
    k1_freq<<<dim3(16,64,BATCH), blk>>>(rgb, dep);
    k2_smooth<<<dim3(16,64,BATCH*2), blk>>>();
    k3_conv<<<dim3(16,64,BATCH), 256>>>(w1,b1,gam,bet,mu,var,w2,b2);
    k4_resize<<<dim3(32,128,BATCH), blk>>>(masks);
    k5_peaks<<<dim3(16,64,BATCH), blk>>>();
    cudaFuncSetAttribute(k6_points, cudaFuncAttributeMaxDynamicSharedMemorySize, 86528);
    k6_points<<<BATCH, 1024, 86528>>>(out);
    k8_boxes<<<BATCH, 1024>>>(out);
}

// round 4
// speedup vs baseline: 2.0707x; 1.3550x over previous
#include <cuda_runtime.h>
#include <math.h>

#define BATCH 8
#define HW 1024
#define HS 512
#define NPIX (HS*HS)
#define NPTS 10
#define KP 512
#define SORTN 8192

// ---------------- scratch (device globals; no allocation) ----------------
__device__ float g_freq[BATCH*12*NPIX];      // 12-ch frequency stack at 512x512
__device__ float g_sal[BATCH*NPIX];          // saliency 512x512
__device__ float g_cand_val[BATCH*NPIX];     // peak candidates
__device__ int   g_cand_idx[BATCH*NPIX];
__device__ int   g_cand_cnt[BATCH];
__device__ int   g_rowflag[BATCH*HW];
__device__ int   g_colflag[BATCH*HW];

// ---------------- packed f32x2 helpers ----------------
__device__ __forceinline__ unsigned long long fma2(unsigned long long a,
                                                   unsigned long long b,
                                                   unsigned long long c){
    unsigned long long d;
    asm("fma.rn.f32x2 %0, %1, %2, %3;" : "=l"(d) : "l"(a), "l"(b), "l"(c));
    return d;
}
__device__ __forceinline__ unsigned long long pack2(float v){
    unsigned long long d;
    asm("mov.b64 %0, {%1, %1};" : "=l"(d) : "f"(v));
    return d;
}
__device__ __forceinline__ void unpack2(unsigned long long p, float& lo, float& hi){
    asm("mov.b64 {%0, %1}, %2;" : "=f"(lo), "=f"(hi) : "l"(p));
}

// ---------------- K0: zero counters/flags ----------------
__global__ void k0_zero(){
    int i = blockIdx.x*256 + threadIdx.x;
    if (i < BATCH) g_cand_cnt[i] = 0;
    if (i < BATCH*HW){ g_rowflag[i] = 0; g_colflag[i] = 0; }
}

// ---------------- K1: gray + Haar DWT + energy (freq ch 0..9) ----------------
__global__ void k1_freq(const float* __restrict__ rgb, const float* __restrict__ dep){
    int x = blockIdx.x*32 + threadIdx.x;
    int y = blockIdx.y*8  + threadIdx.y;
    int b = blockIdx.z;
    size_t plane = (size_t)HW*HW;
    const float2* rp = (const float2*)(rgb + (size_t)b*3*plane);
    const float2* gp = rp + plane/2;
    const float2* bp = gp + plane/2;
    const float2* dp = (const float2*)(dep + (size_t)b*plane);
    int r0 = y*HW + x;
    int r1 = r0 + HW/2;
    float2 ra = rp[r0], rb = rp[r1], ga = gp[r0], gb = gp[r1], ba = bp[r0], bb = bp[r1];
    float v00 = (ra.x+ga.x+ba.x)/3.0f;
    float v01 = (ra.y+ga.y+ba.y)/3.0f;
    float v10 = (rb.x+gb.x+bb.x)/3.0f;
    float v11 = (rb.y+gb.y+bb.y)/3.0f;
    int p = y*HS + x;
    float* F = g_freq + (size_t)b*12*NPIX;
    {
        float a=v00*0.5f, c=v10*0.5f, e=v01*0.5f, f=v11*0.5f;
        float LL=a+c, LH=a-c, HL=e+f, HH=e-f;
        F[0*NPIX+p]=LL; F[1*NPIX+p]=LH; F[2*NPIX+p]=HL; F[3*NPIX+p]=HH;
        F[8*NPIX+p]=sqrtf(LH*LH+HL*HL+HH*HH+1e-8f);
    }
    {
        float2 da = dp[r0], db = dp[r1];
        float a=da.x*0.5f, c=db.x*0.5f, e=da.y*0.5f, f=db.y*0.5f;
        float LL=a+c, LH=a-c, HL=e+f, HH=e-f;
        F[4*NPIX+p]=LL; F[5*NPIX+p]=LH; F[6*NPIX+p]=HL; F[7*NPIX+p]=HH;
        F[9*NPIX+p]=sqrtf(LH*LH+HL*HL+HH*HH+1e-8f);
    }
}

// ---------------- K2: separable 5x5 gaussian with smem tiling (-> ch 10,11) ----------------
__global__ void k2_smooth(){
    __shared__ float tile[12][36];
    __shared__ float hbuf[12][32];
    int tx = threadIdx.x, ty = threadIdx.y;
    int tid = ty*32 + tx;
    // normalized 1D kernel (separable == reference 2D outer product / sum)
    const float e0 = 1.0f, e1 = 0.60653065971f, e2 = 0.13533528323f;
    const float sum1 = e0 + 2.f*e1 + 2.f*e2;
    const float w0 = e0/sum1, w1 = e1/sum1, w2 = e2/sum1;
    int x0 = blockIdx.x*32, y0 = blockIdx.y*8;
    int b = blockIdx.z >> 1, e = blockIdx.z & 1;
    const float* src = g_freq + ((size_t)b*12 + 8 + e)*NPIX;
    for (int l = tid; l < 12*36; l += 256){
        int r = l/36, c = l%36;
        int gy = y0 + r - 2, gx = x0 + c - 2;
        float v = 0.f;
        if (gy >= 0 && gy < HS && gx >= 0 && gx < HS) v = src[gy*HS + gx];
        tile[r][c] = v;
    }
    __syncthreads();
    for (int l = tid; l < 12*32; l += 256){
        int r = l/32, c = l%32;
        hbuf[r][c] = w2*(tile[r][c] + tile[r][c+4]) + w1*(tile[r][c+1] + tile[r][c+3]) + w0*tile[r][c+2];
    }
    __syncthreads();
    float acc = w2*(hbuf[ty][tx] + hbuf[ty+4][tx]) + w1*(hbuf[ty+1][tx] + hbuf[ty+3][tx]) + w0*hbuf[ty+2][tx];
    g_freq[((size_t)b*12 + 10 + e)*NPIX + (y0+ty)*HS + (x0+tx)] = acc;
}

// ---------------- K3: fused conv+BN+GELU+conv1x1+sigmoid, f32x2, 2 px/thread ----------------
__global__ __launch_bounds__(256, 1) void k3_conv(
    const float* __restrict__ w1, const float* __restrict__ b1,
    const float* __restrict__ gam, const float* __restrict__ bet,
    const float* __restrict__ mu,  const float* __restrict__ var,
    const float* __restrict__ w2,  const float* __restrict__ b2)
{
    __shared__ float sIn[12*18*34];             // 18 rows x 34 cols per channel
    __shared__ __align__(16) float sW[3456];
    __shared__ float sSc[32], sSh[32], sW2[32];
    __shared__ float sB2;
    int tid = threadIdx.x;
    int b = blockIdx.z;
    int ty0 = blockIdx.y*16, tx0 = blockIdx.x*32;
    const float* F = g_freq + (size_t)b*12*NPIX;
    for (int l = tid; l < 12*612; l += 256){
        int c = l/612, r = l%612, iy = r/34, ix = r%34;
        int gy = ty0 + iy - 1, gx = tx0 + ix - 1;
        float v = 0.f;
        if (gy >= 0 && gy < HS && gx >= 0 && gx < HS) v = F[(size_t)c*NPIX + gy*HS + gx];
        sIn[l] = v;
    }
    for (int l = tid; l < 3456; l += 256){
        int tl = l >> 5, oc = l & 31;
        sW[l] = w1[oc*108 + tl];               // sW[(c*9+tap)*32 + oc]
    }
    if (tid < 32){
        float inv = 1.0f/sqrtf(var[tid] + 1e-5f);
        float sc = gam[tid]*inv;
        sSc[tid] = sc;
        sSh[tid] = (b1[tid] - mu[tid])*sc + bet[tid];
        sW2[tid] = w2[tid];
    }
    if (tid == 0) sB2 = b2[0];
    __syncthreads();
    int ty = tid >> 5, tx = tid & 31;          // pixel A: (ty, tx); pixel B: (ty+8, tx)
    unsigned long long accA[16], accB[16];     // acc[j] = channels {2j, 2j+1}
    #pragma unroll
    for (int i=0;i<16;i++){ accA[i] = 0ULL; accB[i] = 0ULL; }
    const ulonglong2* sWu = reinterpret_cast<const ulonglong2*>(sW);
    for (int c=0; c<12; c++){
        #pragma unroll
        for (int tap=0; tap<9; tap++){
            int ky = tap/3, kx = tap%3;
            float a0 = sIn[c*612 + (ty+ky)*34 + (tx+kx)];
            float a1 = sIn[c*612 + (ty+8+ky)*34 + (tx+kx)];
            unsigned long long v0 = pack2(a0), v1 = pack2(a1);
            const ulonglong2* wrow = sWu + (c*9+tap)*8;
            #pragma unroll
            for (int q=0;q<8;q++){
                ulonglong2 wp = wrow[q];
                accA[2*q+0] = fma2(v0, wp.x, accA[2*q+0]);
                accA[2*q+1] = fma2(v0, wp.y, accA[2*q+1]);
                accB[2*q+0] = fma2(v1, wp.x, accB[2*q+0]);
                accB[2*q+1] = fma2(v1, wp.y, accB[2*q+1]);
            }
        }
    }
    float zA = sB2, zB = sB2;
    #pragma unroll
    for (int j=0; j<16; j++){
        float a0, a1, b0, b1v;
        unpack2(accA[j], a0, a1);
        unpack2(accB[j], b0, b1v);
        int oc = 2*j;
        {
            float xv = fmaf(a0, sSc[oc], sSh[oc]);
            float gl = 0.5f*xv*(1.0f + tanhf(0.7978845608f*(xv + 0.044715f*xv*xv*xv)));
            zA = fmaf(gl, sW2[oc], zA);
        }
        {
            float xv = fmaf(a1, sSc[oc+1], sSh[oc+1]);
            float gl = 0.5f*xv*(1.0f + tanhf(0.7978845608f*(xv + 0.044715f*xv*xv*xv)));
            zA = fmaf(gl, sW2[oc+1], zA);
        }
        {
            float xv = fmaf(b0, sSc[oc], sSh[oc]);
            float gl = 0.5f*xv*(1.0f + tanhf(0.7978845608f*(xv + 0.044715f*xv*xv*xv)));
            zB = fmaf(gl, sW2[oc], zB);
        }
        {
            float xv = fmaf(b1v, sSc[oc+1], sSh[oc+1]);
            float gl = 0.5f*xv*(1.0f + tanhf(0.7978845608f*(xv + 0.044715f*xv*xv*xv)));
            zB = fmaf(gl, sW2[oc+1], zB);
        }
    }
    float* S = g_sal + (size_t)b*NPIX;
    S[(ty0+ty)*HS + (tx0+tx)]     = 1.0f/(1.0f + expf(-zA));
    S[(ty0+ty+8)*HS + (tx0+tx)]   = 1.0f/(1.0f + expf(-zB));
}

// ---------------- K45: fused bilinear x2 upsample + flags + peak detection ----------------
__global__ void k45_mask_peaks(float* __restrict__ masks){
    __shared__ int colAny[64];
    __shared__ int rowAny[16];
    int tx = threadIdx.x, ty = threadIdx.y;
    int tid = ty*32 + tx;
    if (tid < 64) colAny[tid] = 0;
    if (tid < 16) rowAny[tid] = 0;
    __syncthreads();
    int x = blockIdx.x*32 + tx;
    int y = blockIdx.y*8  + ty;
    int b = blockIdx.z;
    const float* s = g_sal + (size_t)b*NPIX;
    int xm = max(x-1,0), xp = min(x+1,HS-1);
    int ym = max(y-1,0), yp = min(y+1,HS-1);
    float n00=s[ym*HS+xm], n01=s[ym*HS+x], n02=s[ym*HS+xp];
    float n10=s[y*HS+xm],  v  =s[y*HS+x],  n12=s[y*HS+xp];
    float n20=s[yp*HS+xm], n21=s[yp*HS+x], n22=s[yp*HS+xp];
    // --- peak detection (clamped duplicates can't exceed in-window max) ---
    float mp = fmaxf(fmaxf(fmaxf(n00,n01),fmaxf(n02,n10)),
                     fmaxf(fmaxf(v,n12),fmaxf(fmaxf(n20,n21),n22)));
    bool pk = (v == mp) && (v > 0.f);
    unsigned m = __ballot_sync(0xffffffffu, pk);
    if (m){
        int lane = tx;
        int leader = __ffs(m) - 1;
        int base = 0;
        if (lane == leader) base = atomicAdd(&g_cand_cnt[b], __popc(m));
        base = __shfl_sync(0xffffffffu, base, leader);
        if (pk){
            int r = __popc(m & ((1u << lane) - 1u));
            g_cand_val[(size_t)b*NPIX + base + r] = v;
            g_cand_idx[(size_t)b*NPIX + base + r] = y*HS + x;
        }
    }
    // --- bilinear x2: outputs (2x,2y),(2x+1,2y),(2x,2y+1),(2x+1,2y+1) ---
    // X=2x  : wx=0.75 over cols (x-1, x); X=2x+1: wx=0.25 over cols (x, x+1)
    float m00 = 0.25f*(0.25f*n00 + 0.75f*n01) + 0.75f*(0.25f*n10 + 0.75f*v);   // (2x,2y)
    float m01 = 0.25f*(0.75f*n01 + 0.25f*n02) + 0.75f*(0.75f*v + 0.25f*n12);   // (2x+1,2y)
    float m10 = 0.75f*(0.25f*n10 + 0.75f*v)   + 0.25f*(0.25f*n20 + 0.75f*n21); // (2x,2y+1)
    float m11 = 0.75f*(0.75f*v + 0.25f*n12)   + 0.25f*(0.75f*n21 + 0.25f*n22); // (2x+1,2y+1)
    float* M = masks + (size_t)b*HW*HW;
    *(float2*)&M[(size_t)(2*y)*HW   + 2*x] = make_float2(m00, m01);
    *(float2*)&M[(size_t)(2*y+1)*HW + 2*x] = make_float2(m10, m11);
    bool r0 = (m00 > 0.5f) || (m01 > 0.5f);
    bool r1 = (m10 > 0.5f) || (m11 > 0.5f);
    bool c0 = (m00 > 0.5f) || (m10 > 0.5f);
    bool c1 = (m01 > 0.5f) || (m11 > 0.5f);
    if (r0) rowAny[2*ty] = 1;
    if (r1) rowAny[2*ty+1] = 1;
    if (c0) colAny[2*tx] = 1;
    if (c1) colAny[2*tx+1] = 1;
    __syncthreads();
    if (tid < 16 && rowAny[tid]) atomicOr(&g_rowflag[b*HW + blockIdx.y*16 + tid], 1);
    if (tid < 64 && colAny[tid]) atomicOr(&g_colflag[b*HW + blockIdx.x*64 + tid], 1);
}

// ---------------- K6: select top-512 + parallel NMS + fallback top-10 + coords ----------------
// smem layout (dynamic, 86528 B):
//   [0, 65536)        u64 keys[8192]
//   [65536, 81920)    u32 hist[4096]      (reused as u64 bestkey[1024] after hist phase)
//   [81920, 86016)    int part[1024]
//   [86016, 86528)    u8  avail[512]
__global__ __launch_bounds__(1024) void k6_points(float* __restrict__ out){
    extern __shared__ unsigned char sraw[];
    unsigned long long* keys = (unsigned long long*)sraw;
    unsigned int* hist = (unsigned int*)(sraw + 65536);
    unsigned long long* bestkey = (unsigned long long*)(sraw + 65536);
    int* part = (int*)(sraw + 81920);
    unsigned char* avail = (unsigned char*)(sraw + 86016);
    __shared__ int s_ti[KP];
    __shared__ int sT, sM, sCnt, sPick, sCur;
    __shared__ int chosenIdx[NPTS];
    __shared__ int fbIdx[NPTS];
    __shared__ unsigned long long sWin;

    int b = blockIdx.x, tid = threadIdx.x;
    int N = g_cand_cnt[b];
    if (N > NPIX) N = NPIX;
    int need = min(KP, N);

    hist[tid] = 0u; hist[tid+1024] = 0u; hist[tid+2048] = 0u; hist[tid+3072] = 0u;
    if (tid == 0){ sT = 0; sM = 0; }
    __syncthreads();
    const float* cv = g_cand_val + (size_t)b*NPIX;
    const int*   ci = g_cand_idx + (size_t)b*NPIX;
    for (int i = tid; i < N; i += 1024){
        int bin = max(0, min(4095, (int)(cv[i]*4096.0f)));
        atomicAdd(&hist[bin], 1u);
    }
    __syncthreads();
    int t4 = tid*4;
    int h0 = hist[t4], h1 = hist[t4+1], h2 = hist[t4+2], h3 = hist[t4+3];
    part[tid] = h0+h1+h2+h3;
    __syncthreads();
    for (int d = 1; d < 1024; d <<= 1){
        int v = (tid + d < 1024) ? part[tid + d] : 0;
        __syncthreads();
        part[tid] += v;
        __syncthreads();
    }
    {
        int base = part[tid];
        int s1 = base - h0, s2 = s1 - h1, s3 = s2 - h2;
        int bestT = -1;
        if (s3 >= need) bestT = t4+3;
        else if (s2 >= need) bestT = t4+2;
        else if (s1 >= need) bestT = t4+1;
        else if (base >= need) bestT = t4;
        if (bestT >= 0) atomicMax(&sT, bestT);
    }
    __syncthreads();
    int T = sT;
    for (int i = tid; i < N; i += 1024){
        float v = cv[i];
        int bin = max(0, min(4095, (int)(v*4096.0f)));
        if (bin >= T){
            int p = atomicAdd(&sM, 1);
            if (p < SORTN)
                keys[p] = ((unsigned long long)__float_as_uint(v) << 32)
                        | (unsigned int)(~(unsigned)ci[i]);
        }
    }
    __syncthreads();
    int M = min(sM, SORTN);
    for (int i = M + tid; i < SORTN; i += 1024) keys[i] = 0ULL;
    __syncthreads();
    for (int k = 2; k <= SORTN; k <<= 1){
        for (int j = k >> 1; j > 0; j >>= 1){
            #pragma unroll
            for (int r = 0; r < SORTN/1024; r++){
                int i = r*1024 + tid;
                int ixj = i ^ j;
                if (ixj > i){
                    unsigned long long a = keys[i], c = keys[ixj];
                    bool up = ((i & k) == 0);
                    if ((a > c) == up){ keys[i] = c; keys[ixj] = a; }
                }
            }
            __syncthreads();
        }
    }
    // extract sorted top-KP indices in parallel
    if (tid < KP){
        s_ti[tid] = (int)(~(unsigned)(keys[SORTN-1-tid] & 0xffffffffu));
        avail[tid] = 1;
    }
    __syncthreads();

    // ---- fallback: per-thread register top-10 over non-peak pixels ----
    const float* s = g_sal + (size_t)b*NPIX;
    float lv[NPTS]; int li[NPTS];
    #pragma unroll
    for (int k=0;k<NPTS;k++){ lv[k] = -1e30f; li[k] = 0x7fffffff; }
    for (int p = tid; p < NPIX; p += 1024){
        float v = s[p];
        if (v <= lv[NPTS-1]) continue;
        int y = p >> 9, x = p & (HS-1);
        float mp = v;
        #pragma unroll
        for (int dy=-1; dy<=1; dy++){
            int yy = y + dy; if (yy < 0 || yy >= HS) continue;
            #pragma unroll
            for (int dx=-1; dx<=1; dx++){
                int xx = x + dx; if (xx < 0 || xx >= HS) continue;
                mp = fmaxf(mp, s[yy*HS + xx]);
            }
        }
        if (v == mp) continue;
        float cvv = v; int cix = p;
        #pragma unroll
        for (int k=0;k<NPTS;k++){
            bool better = (cvv > lv[k]) || (cvv == lv[k] && cix < li[k]);
            float tv = lv[k]; int ti = li[k];
            if (better){ lv[k] = cvv; li[k] = cix; cvv = tv; cix = ti; }
        }
    }
    int ptr = 0;
    for (int r = 0; r < NPTS; r++){
        unsigned long long mykey = 0ULL;
        if (ptr < NPTS && lv[ptr] > -1e29f)
            mykey = ((unsigned long long)__float_as_uint(lv[ptr]) << 32)
                  | (unsigned int)(~(unsigned)li[ptr]);
        bestkey[tid] = mykey;
        __syncthreads();
        for (int st = 512; st > 0; st >>= 1){
            if (tid < st){
                unsigned long long o = bestkey[tid+st];
                if (o > bestkey[tid]) bestkey[tid] = o;
            }
            __syncthreads();
        }
        unsigned long long win = bestkey[0];
        if (tid == 0){ fbIdx[r] = (int)(~(unsigned)(win & 0xffffffffu)); sWin = win; }
        __syncthreads();
        if (mykey != 0ULL && mykey == sWin) ptr++;
        __syncthreads();
    }

    // ---- greedy NMS: tid0 advances cursor, 512 threads suppress in parallel ----
    int Kv = min(N, KP);
    if (tid == 0){ sCnt = 0; sCur = 0; }
    __syncthreads();
    for (int round = 0; round < NPTS; round++){
        if (tid == 0){
            int i = sCur;
            while (i < Kv && !avail[i]) i++;
            if (i < Kv){
                chosenIdx[sCnt] = s_ti[i];
                sCnt++;
                sPick = i;
                sCur = i + 1;
            } else sPick = -1;
        }
        __syncthreads();
        int i = sPick;
        if (i < 0) break;
        int idx = s_ti[i];
        int xi = idx & (HS-1), yi = idx >> 9;
        if (tid < KP && tid > i && tid < Kv && avail[tid]){
            int dx = (s_ti[tid] & (HS-1)) - xi;
            int dy = (s_ti[tid] >> 9) - yi;
            if (dx*dx + dy*dy < 625) avail[tid] = 0;
        }
        __syncthreads();
    }
    if (tid < NPTS){
        int cnt = sCnt;
        int si = (tid < cnt) ? chosenIdx[tid] : fbIdx[tid - cnt];
        out[b*20 + tid*2 + 0] = (float)(si & (HS-1)) * (1.0f/512.0f);
        out[b*20 + tid*2 + 1] = (float)(si >> 9)     * (1.0f/512.0f);
        out[BATCH*NPTS*2 + b*NPTS + tid] = 1.0f;
    }
}

// ---------------- K8: boxes from row/col flags (parallel reductions) ----------------
__global__ __launch_bounds__(1024) void k8_boxes(float* __restrict__ out){
    __shared__ int sred[1024];
    int b = blockIdx.x, tid = threadIdx.x;
    int rf = g_rowflag[b*HW + tid];
    int cf = g_colflag[b*HW + tid];
    int res[4];
    int init[4] = { rf ? tid : HW, rf ? tid : -1, cf ? tid : HW, cf ? tid : -1 };
    #pragma unroll
    for (int w = 0; w < 4; w++){
        sred[tid] = init[w];
        __syncthreads();
        for (int st = 512; st > 0; st >>= 1){
            if (tid < st){
                int o = sred[tid+st];
                sred[tid] = (w == 0 || w == 2) ? min(sred[tid], o) : max(sred[tid], o);
            }
            __syncthreads();
        }
        res[w] = sred[0];
        __syncthreads();
    }
    if (tid == 0){
        float* bx = out + BATCH*NPTS*2 + BATCH*NPTS + b*4;
        if (res[1] >= 0){ bx[0]=(float)res[2]; bx[1]=(float)res[0]; bx[2]=(float)res[3]; bx[3]=(float)res[1]; }
        else            { bx[0]=0.f; bx[1]=0.f; bx[2]=(float)(HW-1); bx[3]=(float)(HW-1); }
    }
}

// ---------------- launch ----------------
extern "C" void kernel_launch(void* const* d_in, const int* in_sizes, int n_in,
                              void* d_out, int out_size){
    (void)in_sizes; (void)n_in; (void)out_size;
    const float* rgb = (const float*)d_in[0];
    const float* dep = (const float*)d_in[1];
    const float* w1  = (const float*)d_in[2];
    const float* b1  = (const float*)d_in[3];
    const float* gam = (const float*)d_in[4];
    const float* bet = (const float*)d_in[5];
    const float* mu  = (const float*)d_in[6];
    const float* var = (const float*)d_in[7];
    const float* w2  = (const float*)d_in[8];
    const float* b2  = (const float*)d_in[9];
    float* out = (float*)d_out;
    float* masks = out + (BATCH*NPTS*2 + BATCH*NPTS + BATCH*4);  // 272

    dim3 blk(32,8);
    k0_zero<<<(BATCH*HW + 255)/256, 256>>>();
    k1_freq<<<dim3(16,64,BATCH), blk>>>(rgb, dep);
    k2_smooth<<<dim3(16,64,BATCH*2), blk>>>();
    k3_conv<<<dim3(16,32,BATCH), 256>>>(w1,b1,gam,bet,mu,var,w2,b2);
    k45_mask_peaks<<<dim3(16,64,BATCH), blk>>>(masks);
    cudaFuncSetAttribute(k6_points, cudaFuncAttributeMaxDynamicSharedMemorySize, 86528);
    k6_points<<<BATCH, 1024, 86528>>>(out);
    k8_boxes<<<BATCH, 1024>>>(out);
}

// round 5
// speedup vs baseline: 2.3089x; 1.1150x over previous
#include <cuda_runtime.h>
#include <math.h>

#define BATCH 8
#define HW 1024
#define HS 512
#define NPIX (HS*HS)
#define NPTS 10
#define KP 512
#define SORTN 8192

// ---------------- scratch (device globals; no allocation) ----------------
__device__ float g_freq[BATCH*12*NPIX];      // 12-ch frequency stack at 512x512
__device__ float g_sal[BATCH*NPIX];          // saliency 512x512
__device__ float g_cand_val[BATCH*NPIX];     // peak candidates
__device__ int   g_cand_idx[BATCH*NPIX];
__device__ int   g_cand_cnt[BATCH];
__device__ int   g_rowflag[BATCH*HW];
__device__ int   g_colflag[BATCH*HW];

// ---------------- packed f32x2 helpers ----------------
__device__ __forceinline__ unsigned long long fma2(unsigned long long a,
                                                   unsigned long long b,
                                                   unsigned long long c){
    unsigned long long d;
    asm("fma.rn.f32x2 %0, %1, %2, %3;" : "=l"(d) : "l"(a), "l"(b), "l"(c));
    return d;
}
__device__ __forceinline__ unsigned long long pack2(float v){
    unsigned long long d;
    asm("mov.b64 %0, {%1, %1};" : "=l"(d) : "f"(v));
    return d;
}
__device__ __forceinline__ void unpack2(unsigned long long p, float& lo, float& hi){
    asm("mov.b64 {%0, %1}, %2;" : "=f"(lo), "=f"(hi) : "l"(p));
}

// ---------------- K0: zero counters/flags ----------------
__global__ void k0_zero(){
    int i = blockIdx.x*256 + threadIdx.x;
    if (i < BATCH) g_cand_cnt[i] = 0;
    if (i < BATCH*HW){ g_rowflag[i] = 0; g_colflag[i] = 0; }
}

// ---------------- K1: gray + Haar DWT + energy (freq ch 0..9) ----------------
__global__ void k1_freq(const float* __restrict__ rgb, const float* __restrict__ dep){
    int x = blockIdx.x*32 + threadIdx.x;
    int y = blockIdx.y*8  + threadIdx.y;
    int b = blockIdx.z;
    size_t plane = (size_t)HW*HW;
    const float2* rp = (const float2*)(rgb + (size_t)b*3*plane);
    const float2* gp = rp + plane/2;
    const float2* bp = gp + plane/2;
    const float2* dp = (const float2*)(dep + (size_t)b*plane);
    int r0 = y*HW + x;
    int r1 = r0 + HW/2;
    float2 ra = rp[r0], rb = rp[r1], ga = gp[r0], gb = gp[r1], ba = bp[r0], bb = bp[r1];
    float v00 = (ra.x+ga.x+ba.x)/3.0f;
    float v01 = (ra.y+ga.y+ba.y)/3.0f;
    float v10 = (rb.x+gb.x+bb.x)/3.0f;
    float v11 = (rb.y+gb.y+bb.y)/3.0f;
    int p = y*HS + x;
    float* F = g_freq + (size_t)b*12*NPIX;
    {
        float a=v00*0.5f, c=v10*0.5f, e=v01*0.5f, f=v11*0.5f;
        float LL=a+c, LH=a-c, HL=e+f, HH=e-f;
        F[0*NPIX+p]=LL; F[1*NPIX+p]=LH; F[2*NPIX+p]=HL; F[3*NPIX+p]=HH;
        F[8*NPIX+p]=sqrtf(LH*LH+HL*HL+HH*HH+1e-8f);
    }
    {
        float2 da = dp[r0], db = dp[r1];
        float a=da.x*0.5f, c=db.x*0.5f, e=da.y*0.5f, f=db.y*0.5f;
        float LL=a+c, LH=a-c, HL=e+f, HH=e-f;
        F[4*NPIX+p]=LL; F[5*NPIX+p]=LH; F[6*NPIX+p]=HL; F[7*NPIX+p]=HH;
        F[9*NPIX+p]=sqrtf(LH*LH+HL*HL+HH*HH+1e-8f);
    }
}

// ---------------- K2: separable 5x5 gaussian with smem tiling (-> ch 10,11) ----------------
__global__ void k2_smooth(){
    __shared__ float tile[12][36];
    __shared__ float hbuf[12][32];
    int tx = threadIdx.x, ty = threadIdx.y;
    int tid = ty*32 + tx;
    const float e0 = 1.0f, e1 = 0.60653065971f, e2 = 0.13533528323f;
    const float sum1 = e0 + 2.f*e1 + 2.f*e2;
    const float w0 = e0/sum1, w1 = e1/sum1, w2 = e2/sum1;
    int x0 = blockIdx.x*32, y0 = blockIdx.y*8;
    int b = blockIdx.z >> 1, e = blockIdx.z & 1;
    const float* src = g_freq + ((size_t)b*12 + 8 + e)*NPIX;
    for (int l = tid; l < 12*36; l += 256){
        int r = l/36, c = l%36;
        int gy = y0 + r - 2, gx = x0 + c - 2;
        float v = 0.f;
        if (gy >= 0 && gy < HS && gx >= 0 && gx < HS) v = src[gy*HS + gx];
        tile[r][c] = v;
    }
    __syncthreads();
    for (int l = tid; l < 12*32; l += 256){
        int r = l/32, c = l%32;
        hbuf[r][c] = w2*(tile[r][c] + tile[r][c+4]) + w1*(tile[r][c+1] + tile[r][c+3]) + w0*tile[r][c+2];
    }
    __syncthreads();
    float acc = w2*(hbuf[ty][tx] + hbuf[ty+4][tx]) + w1*(hbuf[ty+1][tx] + hbuf[ty+3][tx]) + w0*hbuf[ty+2][tx];
    g_freq[((size_t)b*12 + 10 + e)*NPIX + (y0+ty)*HS + (x0+tx)] = acc;
}

// ---------------- K3: fused conv+BN+GELU+conv1x1+sigmoid, f32x2, 2 px/thread ----------------
__global__ __launch_bounds__(256, 1) void k3_conv(
    const float* __restrict__ w1, const float* __restrict__ b1,
    const float* __restrict__ gam, const float* __restrict__ bet,
    const float* __restrict__ mu,  const float* __restrict__ var,
    const float* __restrict__ w2,  const float* __restrict__ b2)
{
    __shared__ float sIn[12*18*34];
    __shared__ __align__(16) float sW[3456];
    __shared__ float sSc[32], sSh[32], sW2[32];
    __shared__ float sB2;
    int tid = threadIdx.x;
    int b = blockIdx.z;
    int ty0 = blockIdx.y*16, tx0 = blockIdx.x*32;
    const float* F = g_freq + (size_t)b*12*NPIX;
    for (int l = tid; l < 12*612; l += 256){
        int c = l/612, r = l%612, iy = r/34, ix = r%34;
        int gy = ty0 + iy - 1, gx = tx0 + ix - 1;
        float v = 0.f;
        if (gy >= 0 && gy < HS && gx >= 0 && gx < HS) v = F[(size_t)c*NPIX + gy*HS + gx];
        sIn[l] = v;
    }
    for (int l = tid; l < 3456; l += 256){
        int tl = l >> 5, oc = l & 31;
        sW[l] = w1[oc*108 + tl];
    }
    if (tid < 32){
        float inv = 1.0f/sqrtf(var[tid] + 1e-5f);
        float sc = gam[tid]*inv;
        sSc[tid] = sc;
        sSh[tid] = (b1[tid] - mu[tid])*sc + bet[tid];
        sW2[tid] = w2[tid];
    }
    if (tid == 0) sB2 = b2[0];
    __syncthreads();
    int ty = tid >> 5, tx = tid & 31;
    unsigned long long accA[16], accB[16];
    #pragma unroll
    for (int i=0;i<16;i++){ accA[i] = 0ULL; accB[i] = 0ULL; }
    const ulonglong2* sWu = reinterpret_cast<const ulonglong2*>(sW);
    for (int c=0; c<12; c++){
        #pragma unroll
        for (int tap=0; tap<9; tap++){
            int ky = tap/3, kx = tap%3;
            float a0 = sIn[c*612 + (ty+ky)*34 + (tx+kx)];
            float a1 = sIn[c*612 + (ty+8+ky)*34 + (tx+kx)];
            unsigned long long v0 = pack2(a0), v1 = pack2(a1);
            const ulonglong2* wrow = sWu + (c*9+tap)*8;
            #pragma unroll
            for (int q=0;q<8;q++){
                ulonglong2 wp = wrow[q];
                accA[2*q+0] = fma2(v0, wp.x, accA[2*q+0]);
                accA[2*q+1] = fma2(v0, wp.y, accA[2*q+1]);
                accB[2*q+0] = fma2(v1, wp.x, accB[2*q+0]);
                accB[2*q+1] = fma2(v1, wp.y, accB[2*q+1]);
            }
        }
    }
    float zA = sB2, zB = sB2;
    #pragma unroll
    for (int j=0; j<16; j++){
        float a0, a1, b0, b1v;
        unpack2(accA[j], a0, a1);
        unpack2(accB[j], b0, b1v);
        int oc = 2*j;
        {
            float xv = fmaf(a0, sSc[oc], sSh[oc]);
            float gl = 0.5f*xv*(1.0f + tanhf(0.7978845608f*(xv + 0.044715f*xv*xv*xv)));
            zA = fmaf(gl, sW2[oc], zA);
        }
        {
            float xv = fmaf(a1, sSc[oc+1], sSh[oc+1]);
            float gl = 0.5f*xv*(1.0f + tanhf(0.7978845608f*(xv + 0.044715f*xv*xv*xv)));
            zA = fmaf(gl, sW2[oc+1], zA);
        }
        {
            float xv = fmaf(b0, sSc[oc], sSh[oc]);
            float gl = 0.5f*xv*(1.0f + tanhf(0.7978845608f*(xv + 0.044715f*xv*xv*xv)));
            zB = fmaf(gl, sW2[oc], zB);
        }
        {
            float xv = fmaf(b1v, sSc[oc+1], sSh[oc+1]);
            float gl = 0.5f*xv*(1.0f + tanhf(0.7978845608f*(xv + 0.044715f*xv*xv*xv)));
            zB = fmaf(gl, sW2[oc+1], zB);
        }
    }
    float* S = g_sal + (size_t)b*NPIX;
    S[(ty0+ty)*HS + (tx0+tx)]     = 1.0f/(1.0f + expf(-zA));
    S[(ty0+ty+8)*HS + (tx0+tx)]   = 1.0f/(1.0f + expf(-zB));
}

// ---------------- K45: fused bilinear x2 upsample + flags + peaks (block-local buffer) ----------------
__global__ void k45_mask_peaks(float* __restrict__ masks){
    __shared__ int colAny[64];
    __shared__ int rowAny[16];
    __shared__ float sv[256];
    __shared__ int   si[256];
    __shared__ int   scnt, sbase;
    int tx = threadIdx.x, ty = threadIdx.y;
    int tid = ty*32 + tx;
    if (tid < 64) colAny[tid] = 0;
    if (tid < 16) rowAny[tid] = 0;
    if (tid == 0) scnt = 0;
    __syncthreads();
    int x = blockIdx.x*32 + tx;
    int y = blockIdx.y*8  + ty;
    int b = blockIdx.z;
    const float* s = g_sal + (size_t)b*NPIX;
    int xm = max(x-1,0), xp = min(x+1,HS-1);
    int ym = max(y-1,0), yp = min(y+1,HS-1);
    float n00=s[ym*HS+xm], n01=s[ym*HS+x], n02=s[ym*HS+xp];
    float n10=s[y*HS+xm],  v  =s[y*HS+x],  n12=s[y*HS+xp];
    float n20=s[yp*HS+xm], n21=s[yp*HS+x], n22=s[yp*HS+xp];
    float mp = fmaxf(fmaxf(fmaxf(n00,n01),fmaxf(n02,n10)),
                     fmaxf(fmaxf(v,n12),fmaxf(fmaxf(n20,n21),n22)));
    bool pk = (v == mp) && (v > 0.f);
    if (pk){
        int p = atomicAdd(&scnt, 1);
        sv[p] = v; si[p] = y*HS + x;
    }
    // --- bilinear x2 ---
    float m00 = 0.25f*(0.25f*n00 + 0.75f*n01) + 0.75f*(0.25f*n10 + 0.75f*v);
    float m01 = 0.25f*(0.75f*n01 + 0.25f*n02) + 0.75f*(0.75f*v + 0.25f*n12);
    float m10 = 0.75f*(0.25f*n10 + 0.75f*v)   + 0.25f*(0.25f*n20 + 0.75f*n21);
    float m11 = 0.75f*(0.75f*v + 0.25f*n12)   + 0.25f*(0.75f*n21 + 0.25f*n22);
    float* M = masks + (size_t)b*HW*HW;
    *(float2*)&M[(size_t)(2*y)*HW   + 2*x] = make_float2(m00, m01);
    *(float2*)&M[(size_t)(2*y+1)*HW + 2*x] = make_float2(m10, m11);
    bool r0 = (m00 > 0.5f) || (m01 > 0.5f);
    bool r1 = (m10 > 0.5f) || (m11 > 0.5f);
    bool c0 = (m00 > 0.5f) || (m10 > 0.5f);
    bool c1 = (m01 > 0.5f) || (m11 > 0.5f);
    if (r0) rowAny[2*ty] = 1;
    if (r1) rowAny[2*ty+1] = 1;
    if (c0) colAny[2*tx] = 1;
    if (c1) colAny[2*tx+1] = 1;
    __syncthreads();
    if (tid < 16 && rowAny[tid]) atomicOr(&g_rowflag[b*HW + blockIdx.y*16 + tid], 1);
    if (tid < 64 && colAny[tid]) atomicOr(&g_colflag[b*HW + blockIdx.x*64 + tid], 1);
    if (tid == 0 && scnt) sbase = atomicAdd(&g_cand_cnt[b], scnt);
    __syncthreads();
    if (tid < scnt){
        g_cand_val[(size_t)b*NPIX + sbase + tid] = sv[tid];
        g_cand_idx[(size_t)b*NPIX + sbase + tid] = si[tid];
    }
}

// ---------------- K6: select top-512 + parallel NMS + fallback top-10 + coords ----------------
__global__ __launch_bounds__(1024) void k6_points(float* __restrict__ out){
    extern __shared__ unsigned char sraw[];
    unsigned long long* keys = (unsigned long long*)sraw;
    unsigned int* hist = (unsigned int*)(sraw + 65536);
    unsigned long long* bestkey = (unsigned long long*)(sraw + 65536);
    int* part = (int*)(sraw + 81920);
    unsigned char* avail = (unsigned char*)(sraw + 86016);
    __shared__ int s_ti[KP];
    __shared__ int sT, sM, sCnt, sPick, sCur;
    __shared__ int chosenIdx[NPTS];
    __shared__ int fbIdx[NPTS];
    __shared__ unsigned long long sWin;

    int b = blockIdx.x, tid = threadIdx.x;
    int N = g_cand_cnt[b];
    if (N > NPIX) N = NPIX;
    int need = min(KP, N);

    hist[tid] = 0u; hist[tid+1024] = 0u; hist[tid+2048] = 0u; hist[tid+3072] = 0u;
    if (tid == 0){ sT = 0; sM = 0; }
    __syncthreads();
    const float* cv = g_cand_val + (size_t)b*NPIX;
    const int*   ci = g_cand_idx + (size_t)b*NPIX;
    for (int i = tid; i < N; i += 1024){
        int bin = max(0, min(4095, (int)(cv[i]*4096.0f)));
        atomicAdd(&hist[bin], 1u);
    }
    __syncthreads();
    int t4 = tid*4;
    int h0 = hist[t4], h1 = hist[t4+1], h2 = hist[t4+2], h3 = hist[t4+3];
    part[tid] = h0+h1+h2+h3;
    __syncthreads();
    for (int d = 1; d < 1024; d <<= 1){
        int v = (tid + d < 1024) ? part[tid + d] : 0;
        __syncthreads();
        part[tid] += v;
        __syncthreads();
    }
    {
        int base = part[tid];
        int s1 = base - h0, s2 = s1 - h1, s3 = s2 - h2;
        int bestT = -1;
        if (s3 >= need) bestT = t4+3;
        else if (s2 >= need) bestT = t4+2;
        else if (s1 >= need) bestT = t4+1;
        else if (base >= need) bestT = t4;
        if (bestT >= 0) atomicMax(&sT, bestT);
    }
    __syncthreads();
    int T = sT;
    for (int i = tid; i < N; i += 1024){
        float v = cv[i];
        int bin = max(0, min(4095, (int)(v*4096.0f)));
        if (bin >= T){
            int p = atomicAdd(&sM, 1);
            if (p < SORTN)
                keys[p] = ((unsigned long long)__float_as_uint(v) << 32)
                        | (unsigned int)(~(unsigned)ci[i]);
        }
    }
    __syncthreads();
    int M = min(sM, SORTN);
    // dynamic sort width: smallest power of 2 >= max(512, M)
    int S = 512;
    while (S < M) S <<= 1;
    for (int i = M + tid; i < S; i += 1024) keys[i] = 0ULL;
    __syncthreads();
    for (int k = 2; k <= S; k <<= 1){
        for (int j = k >> 1; j > 0; j >>= 1){
            for (int i = tid; i < S; i += 1024){
                int ixj = i ^ j;
                if (ixj > i){
                    unsigned long long a = keys[i], c = keys[ixj];
                    bool up = ((i & k) == 0);
                    if ((a > c) == up){ keys[i] = c; keys[ixj] = a; }
                }
            }
            __syncthreads();
        }
    }
    if (tid < KP){
        s_ti[tid] = (int)(~(unsigned)(keys[S-1-tid] & 0xffffffffu));
        avail[tid] = 1;
    }
    __syncthreads();

    // ---- fallback: per-thread register top-10 over non-peak pixels ----
    const float* s = g_sal + (size_t)b*NPIX;
    float lv[NPTS]; int li[NPTS];
    #pragma unroll
    for (int k=0;k<NPTS;k++){ lv[k] = -1e30f; li[k] = 0x7fffffff; }
    for (int p = tid; p < NPIX; p += 1024){
        float v = s[p];
        if (v <= lv[NPTS-1]) continue;
        int y = p >> 9, x = p & (HS-1);
        float mp = v;
        #pragma unroll
        for (int dy=-1; dy<=1; dy++){
            int yy = y + dy; if (yy < 0 || yy >= HS) continue;
            #pragma unroll
            for (int dx=-1; dx<=1; dx++){
                int xx = x + dx; if (xx < 0 || xx >= HS) continue;
                mp = fmaxf(mp, s[yy*HS + xx]);
            }
        }
        if (v == mp) continue;
        float cvv = v; int cix = p;
        #pragma unroll
        for (int k=0;k<NPTS;k++){
            bool better = (cvv > lv[k]) || (cvv == lv[k] && cix < li[k]);
            float tv = lv[k]; int ti = li[k];
            if (better){ lv[k] = cvv; li[k] = cix; cvv = tv; cix = ti; }
        }
    }
    int ptr = 0;
    for (int r = 0; r < NPTS; r++){
        unsigned long long mykey = 0ULL;
        if (ptr < NPTS && lv[ptr] > -1e29f)
            mykey = ((unsigned long long)__float_as_uint(lv[ptr]) << 32)
                  | (unsigned int)(~(unsigned)li[ptr]);
        bestkey[tid] = mykey;
        __syncthreads();
        for (int st = 512; st > 0; st >>= 1){
            if (tid < st){
                unsigned long long o = bestkey[tid+st];
                if (o > bestkey[tid]) bestkey[tid] = o;
            }
            __syncthreads();
        }
        unsigned long long win = bestkey[0];
        if (tid == 0){ fbIdx[r] = (int)(~(unsigned)(win & 0xffffffffu)); sWin = win; }
        __syncthreads();
        if (mykey != 0ULL && mykey == sWin) ptr++;
        __syncthreads();
    }

    // ---- greedy NMS: tid0 advances cursor, threads suppress in parallel ----
    int Kv = min(N, KP);
    if (tid == 0){ sCnt = 0; sCur = 0; }
    __syncthreads();
    for (int round = 0; round < NPTS; round++){
        if (tid == 0){
            int i = sCur;
            while (i < Kv && !avail[i]) i++;
            if (i < Kv){
                chosenIdx[sCnt] = s_ti[i];
                sCnt++;
                sPick = i;
                sCur = i + 1;
            } else sPick = -1;
        }
        __syncthreads();
        int i = sPick;
        if (i < 0) break;
        int idx = s_ti[i];
        int xi = idx & (HS-1), yi = idx >> 9;
        if (tid < KP && tid > i && tid < Kv && avail[tid]){
            int dx = (s_ti[tid] & (HS-1)) - xi;
            int dy = (s_ti[tid] >> 9) - yi;
            if (dx*dx + dy*dy < 625) avail[tid] = 0;
        }
        __syncthreads();
    }
    if (tid < NPTS){
        int cnt = sCnt;
        int si = (tid < cnt) ? chosenIdx[tid] : fbIdx[tid - cnt];
        out[b*20 + tid*2 + 0] = (float)(si & (HS-1)) * (1.0f/512.0f);
        out[b*20 + tid*2 + 1] = (float)(si >> 9)     * (1.0f/512.0f);
        out[BATCH*NPTS*2 + b*NPTS + tid] = 1.0f;
    }
}

// ---------------- K8: boxes from row/col flags (parallel reductions) ----------------
__global__ __launch_bounds__(1024) void k8_boxes(float* __restrict__ out){
    __shared__ int sred[1024];
    int b = blockIdx.x, tid = threadIdx.x;
    int rf = g_rowflag[b*HW + tid];
    int cf = g_colflag[b*HW + tid];
    int res[4];
    int init[4] = { rf ? tid : HW, rf ? tid : -1, cf ? tid : HW, cf ? tid : -1 };
    #pragma unroll
    for (int w = 0; w < 4; w++){
        sred[tid] = init[w];
        __syncthreads();
        for (int st = 512; st > 0; st >>= 1){
            if (tid < st){
                int o = sred[tid+st];
                sred[tid] = (w == 0 || w == 2) ? min(sred[tid], o) : max(sred[tid], o);
            }
            __syncthreads();
        }
        res[w] = sred[0];
        __syncthreads();
    }
    if (tid == 0){
        float* bx = out + BATCH*NPTS*2 + BATCH*NPTS + b*4;
        if (res[1] >= 0){ bx[0]=(float)res[2]; bx[1]=(float)res[0]; bx[2]=(float)res[3]; bx[3]=(float)res[1]; }
        else            { bx[0]=0.f; bx[1]=0.f; bx[2]=(float)(HW-1); bx[3]=(float)(HW-1); }
    }
}

// ---------------- launch ----------------
extern "C" void kernel_launch(void* const* d_in, const int* in_sizes, int n_in,
                              void* d_out, int out_size){
    (void)in_sizes; (void)n_in; (void)out_size;
    const float* rgb = (const float*)d_in[0];
    const float* dep = (const float*)d_in[1];
    const float* w1  = (const float*)d_in[2];
    const float* b1  = (const float*)d_in[3];
    const float* gam = (const float*)d_in[4];
    const float* bet = (const float*)d_in[5];
    const float* mu  = (const float*)d_in[6];
    const float* var = (const float*)d_in[7];
    const float* w2  = (const float*)d_in[8];
    const float* b2  = (const float*)d_in[9];
    float* out = (float*)d_out;
    float* masks = out + (BATCH*NPTS*2 + BATCH*NPTS + BATCH*4);  // 272

    dim3 blk(32,8);
    k0_zero<<<(BATCH*HW + 255)/256, 256>>>();
    k1_freq<<<dim3(16,64,BATCH), blk>>>(rgb, dep);
    k2_smooth<<<dim3(16,64,BATCH*2), blk>>>();
    k3_conv<<<dim3(16,32,BATCH), 256>>>(w1,b1,gam,bet,mu,var,w2,b2);
    k45_mask_peaks<<<dim3(16,64,BATCH), blk>>>(masks);
    cudaFuncSetAttribute(k6_points, cudaFuncAttributeMaxDynamicSharedMemorySize, 86528);
    k6_points<<<BATCH, 1024, 86528>>>(out);
    k8_boxes<<<BATCH, 1024>>>(out);
}

// round 6
// speedup vs baseline: 3.2727x; 1.4174x over previous
#include <cuda_runtime.h>
#include <math.h>

#define BATCH 8
#define HW 1024
#define HS 512
#define NPIX (HS*HS)
#define NPTS 10
#define KP 512
#define SORTN 8192

// ---------------- scratch (device globals; no allocation) ----------------
__device__ float g_freq[BATCH*12*NPIX];
__device__ float g_sal[BATCH*NPIX];
__device__ float g_cand_val[BATCH*NPIX];
__device__ int   g_cand_idx[BATCH*NPIX];
__device__ int   g_cand_cnt[BATCH];
__device__ int   g_rowflag[BATCH*HW];
__device__ int   g_colflag[BATCH*HW];

// ---------------- packed f32x2 helpers ----------------
__device__ __forceinline__ unsigned long long fma2(unsigned long long a,
                                                   unsigned long long b,
                                                   unsigned long long c){
    unsigned long long d;
    asm("fma.rn.f32x2 %0, %1, %2, %3;" : "=l"(d) : "l"(a), "l"(b), "l"(c));
    return d;
}
__device__ __forceinline__ unsigned long long pack2(float v){
    unsigned long long d;
    asm("mov.b64 %0, {%1, %1};" : "=l"(d) : "f"(v));
    return d;
}
__device__ __forceinline__ void unpack2(unsigned long long p, float& lo, float& hi){
    asm("mov.b64 {%0, %1}, %2;" : "=f"(lo), "=f"(hi) : "l"(p));
}

// ---------------- K0 ----------------
__global__ void k0_zero(){
    int i = blockIdx.x*256 + threadIdx.x;
    if (i < BATCH) g_cand_cnt[i] = 0;
    if (i < BATCH*HW){ g_rowflag[i] = 0; g_colflag[i] = 0; }
}

// ---------------- K1: gray + Haar DWT + energy (freq ch 0..9) ----------------
__global__ void k1_freq(const float* __restrict__ rgb, const float* __restrict__ dep){
    int x = blockIdx.x*32 + threadIdx.x;
    int y = blockIdx.y*8  + threadIdx.y;
    int b = blockIdx.z;
    size_t plane = (size_t)HW*HW;
    const float2* rp = (const float2*)(rgb + (size_t)b*3*plane);
    const float2* gp = rp + plane/2;
    const float2* bp = gp + plane/2;
    const float2* dp = (const float2*)(dep + (size_t)b*plane);
    int r0 = y*HW + x;
    int r1 = r0 + HW/2;
    float2 ra = rp[r0], rb = rp[r1], ga = gp[r0], gb = gp[r1], ba = bp[r0], bb = bp[r1];
    float v00 = (ra.x+ga.x+ba.x)/3.0f;
    float v01 = (ra.y+ga.y+ba.y)/3.0f;
    float v10 = (rb.x+gb.x+bb.x)/3.0f;
    float v11 = (rb.y+gb.y+bb.y)/3.0f;
    int p = y*HS + x;
    float* F = g_freq + (size_t)b*12*NPIX;
    {
        float a=v00*0.5f, c=v10*0.5f, e=v01*0.5f, f=v11*0.5f;
        float LL=a+c, LH=a-c, HL=e+f, HH=e-f;
        F[0*NPIX+p]=LL; F[1*NPIX+p]=LH; F[2*NPIX+p]=HL; F[3*NPIX+p]=HH;
        F[8*NPIX+p]=sqrtf(LH*LH+HL*HL+HH*HH+1e-8f);
    }
    {
        float2 da = dp[r0], db = dp[r1];
        float a=da.x*0.5f, c=db.x*0.5f, e=da.y*0.5f, f=db.y*0.5f;
        float LL=a+c, LH=a-c, HL=e+f, HH=e-f;
        F[4*NPIX+p]=LL; F[5*NPIX+p]=LH; F[6*NPIX+p]=HL; F[7*NPIX+p]=HH;
        F[9*NPIX+p]=sqrtf(LH*LH+HL*HL+HH*HH+1e-8f);
    }
}

// ---------------- K2: separable 5x5 gaussian (-> ch 10,11) ----------------
__global__ void k2_smooth(){
    __shared__ float tile[12][36];
    __shared__ float hbuf[12][32];
    int tx = threadIdx.x, ty = threadIdx.y;
    int tid = ty*32 + tx;
    const float e0 = 1.0f, e1 = 0.60653065971f, e2 = 0.13533528323f;
    const float sum1 = e0 + 2.f*e1 + 2.f*e2;
    const float w0 = e0/sum1, w1 = e1/sum1, w2 = e2/sum1;
    int x0 = blockIdx.x*32, y0 = blockIdx.y*8;
    int b = blockIdx.z >> 1, e = blockIdx.z & 1;
    const float* src = g_freq + ((size_t)b*12 + 8 + e)*NPIX;
    for (int l = tid; l < 12*36; l += 256){
        int r = l/36, c = l%36;
        int gy = y0 + r - 2, gx = x0 + c - 2;
        float v = 0.f;
        if (gy >= 0 && gy < HS && gx >= 0 && gx < HS) v = src[gy*HS + gx];
        tile[r][c] = v;
    }
    __syncthreads();
    for (int l = tid; l < 12*32; l += 256){
        int r = l/32, c = l%32;
        hbuf[r][c] = w2*(tile[r][c] + tile[r][c+4]) + w1*(tile[r][c+1] + tile[r][c+3]) + w0*tile[r][c+2];
    }
    __syncthreads();
    float acc = w2*(hbuf[ty][tx] + hbuf[ty+4][tx]) + w1*(hbuf[ty+1][tx] + hbuf[ty+3][tx]) + w0*hbuf[ty+2][tx];
    g_freq[((size_t)b*12 + 10 + e)*NPIX + (y0+ty)*HS + (x0+tx)] = acc;
}

// ---------------- K3: fused conv+BN+GELU+conv1x1+sigmoid, f32x2, 4 px/thread ----------------
// dynamic smem layout:
//   [0, 55488)        float sIn[12*34*34]
//   [55488, 69312)    float sW[3456]      (16B aligned)
//   [69312, ...)      sSc[32], sSh[32], sW2[32], sB2
#define K3_SMEM (69312 + 97*4)
__global__ __launch_bounds__(256, 1) void k3_conv(
    const float* __restrict__ w1, const float* __restrict__ b1,
    const float* __restrict__ gam, const float* __restrict__ bet,
    const float* __restrict__ mu,  const float* __restrict__ var,
    const float* __restrict__ w2,  const float* __restrict__ b2)
{
    extern __shared__ unsigned char sm[];
    float* sIn = (float*)sm;
    float* sW  = (float*)(sm + 55488);
    float* sSc = (float*)(sm + 69312);
    float* sSh = sSc + 32;
    float* sW2 = sSh + 32;
    float* sB2 = sW2 + 32;
    int tid = threadIdx.x;
    int b = blockIdx.z;
    int ty0 = blockIdx.y*32, tx0 = blockIdx.x*32;
    const float* F = g_freq + (size_t)b*12*NPIX;
    for (int l = tid; l < 12*1156; l += 256){
        int c = l/1156, r = l%1156, iy = r/34, ix = r%34;
        int gy = ty0 + iy - 1, gx = tx0 + ix - 1;
        float v = 0.f;
        if (gy >= 0 && gy < HS && gx >= 0 && gx < HS) v = F[(size_t)c*NPIX + gy*HS + gx];
        sIn[l] = v;
    }
    for (int l = tid; l < 3456; l += 256){
        int tl = l >> 5, oc = l & 31;
        sW[l] = w1[oc*108 + tl];           // sW[(c*9+tap)*32 + oc]
    }
    if (tid < 32){
        float inv = 1.0f/sqrtf(var[tid] + 1e-5f);
        float sc = gam[tid]*inv;
        sSc[tid] = sc;
        sSh[tid] = (b1[tid] - mu[tid])*sc + bet[tid];
        sW2[tid] = w2[tid];
    }
    if (tid == 0) sB2[0] = b2[0];
    __syncthreads();
    int ty = tid >> 5, tx = tid & 31;     // pixels: rows ty, ty+8, ty+16, ty+24
    unsigned long long acc[4][16];        // acc[k][j] = channels {2j,2j+1} of pixel k
    #pragma unroll
    for (int k=0;k<4;k++)
        #pragma unroll
        for (int j=0;j<16;j++) acc[k][j] = 0ULL;
    const ulonglong2* sWu = reinterpret_cast<const ulonglong2*>(sW);
    for (int c=0; c<12; c++){
        #pragma unroll
        for (int tap=0; tap<9; tap++){
            int ky = tap/3, kx = tap%3;
            const float* row0 = sIn + c*1156 + (ty+ky)*34 + (tx+kx);
            unsigned long long v0 = pack2(row0[0]);
            unsigned long long v1 = pack2(row0[8*34]);
            unsigned long long v2 = pack2(row0[16*34]);
            unsigned long long v3 = pack2(row0[24*34]);
            const ulonglong2* wrow = sWu + (c*9+tap)*8;
            #pragma unroll
            for (int q=0;q<8;q++){
                ulonglong2 wp = wrow[q];
                acc[0][2*q+0] = fma2(v0, wp.x, acc[0][2*q+0]);
                acc[0][2*q+1] = fma2(v0, wp.y, acc[0][2*q+1]);
                acc[1][2*q+0] = fma2(v1, wp.x, acc[1][2*q+0]);
                acc[1][2*q+1] = fma2(v1, wp.y, acc[1][2*q+1]);
                acc[2][2*q+0] = fma2(v2, wp.x, acc[2][2*q+0]);
                acc[2][2*q+1] = fma2(v2, wp.y, acc[2][2*q+1]);
                acc[3][2*q+0] = fma2(v3, wp.x, acc[3][2*q+0]);
                acc[3][2*q+1] = fma2(v3, wp.y, acc[3][2*q+1]);
            }
        }
    }
    float* S = g_sal + (size_t)b*NPIX;
    #pragma unroll
    for (int k=0;k<4;k++){
        float z = sB2[0];
        #pragma unroll
        for (int j=0;j<16;j++){
            float a0, a1;
            unpack2(acc[k][j], a0, a1);
            int oc = 2*j;
            {
                float xv = fmaf(a0, sSc[oc], sSh[oc]);
                float gl = 0.5f*xv*(1.0f + tanhf(0.7978845608f*(xv + 0.044715f*xv*xv*xv)));
                z = fmaf(gl, sW2[oc], z);
            }
            {
                float xv = fmaf(a1, sSc[oc+1], sSh[oc+1]);
                float gl = 0.5f*xv*(1.0f + tanhf(0.7978845608f*(xv + 0.044715f*xv*xv*xv)));
                z = fmaf(gl, sW2[oc+1], z);
            }
        }
        S[(ty0+ty+8*k)*HS + (tx0+tx)] = 1.0f/(1.0f + expf(-z));
    }
}

// ---------------- K45: fused bilinear x2 upsample + flags + peaks ----------------
__global__ void k45_mask_peaks(float* __restrict__ masks){
    __shared__ int colAny[64];
    __shared__ int rowAny[16];
    __shared__ float sv[256];
    __shared__ int   si[256];
    __shared__ int   scnt, sbase;
    int tx = threadIdx.x, ty = threadIdx.y;
    int tid = ty*32 + tx;
    if (tid < 64) colAny[tid] = 0;
    if (tid < 16) rowAny[tid] = 0;
    if (tid == 0) scnt = 0;
    __syncthreads();
    int x = blockIdx.x*32 + tx;
    int y = blockIdx.y*8  + ty;
    int b = blockIdx.z;
    const float* s = g_sal + (size_t)b*NPIX;
    int xm = max(x-1,0), xp = min(x+1,HS-1);
    int ym = max(y-1,0), yp = min(y+1,HS-1);
    float n00=s[ym*HS+xm], n01=s[ym*HS+x], n02=s[ym*HS+xp];
    float n10=s[y*HS+xm],  v  =s[y*HS+x],  n12=s[y*HS+xp];
    float n20=s[yp*HS+xm], n21=s[yp*HS+x], n22=s[yp*HS+xp];
    float mp = fmaxf(fmaxf(fmaxf(n00,n01),fmaxf(n02,n10)),
                     fmaxf(fmaxf(v,n12),fmaxf(fmaxf(n20,n21),n22)));
    bool pk = (v == mp) && (v > 0.f);
    if (pk){
        int p = atomicAdd(&scnt, 1);
        sv[p] = v; si[p] = y*HS + x;
    }
    float m00 = 0.25f*(0.25f*n00 + 0.75f*n01) + 0.75f*(0.25f*n10 + 0.75f*v);
    float m01 = 0.25f*(0.75f*n01 + 0.25f*n02) + 0.75f*(0.75f*v + 0.25f*n12);
    float m10 = 0.75f*(0.25f*n10 + 0.75f*v)   + 0.25f*(0.25f*n20 + 0.75f*n21);
    float m11 = 0.75f*(0.75f*v + 0.25f*n12)   + 0.25f*(0.75f*n21 + 0.25f*n22);
    float* M = masks + (size_t)b*HW*HW;
    *(float2*)&M[(size_t)(2*y)*HW   + 2*x] = make_float2(m00, m01);
    *(float2*)&M[(size_t)(2*y+1)*HW + 2*x] = make_float2(m10, m11);
    bool r0 = (m00 > 0.5f) || (m01 > 0.5f);
    bool r1 = (m10 > 0.5f) || (m11 > 0.5f);
    bool c0 = (m00 > 0.5f) || (m10 > 0.5f);
    bool c1 = (m01 > 0.5f) || (m11 > 0.5f);
    if (r0) rowAny[2*ty] = 1;
    if (r1) rowAny[2*ty+1] = 1;
    if (c0) colAny[2*tx] = 1;
    if (c1) colAny[2*tx+1] = 1;
    __syncthreads();
    if (tid < 16 && rowAny[tid]) atomicOr(&g_rowflag[b*HW + blockIdx.y*16 + tid], 1);
    if (tid < 64 && colAny[tid]) atomicOr(&g_colflag[b*HW + blockIdx.x*64 + tid], 1);
    if (tid == 0 && scnt) sbase = atomicAdd(&g_cand_cnt[b], scnt);
    __syncthreads();
    if (tid < scnt){
        g_cand_val[(size_t)b*NPIX + sbase + tid] = sv[tid];
        g_cand_idx[(size_t)b*NPIX + sbase + tid] = si[tid];
    }
}

// ---------------- K6: two-level select + sort + NMS + conditional fallback ----------------
// smem layout (dynamic, 86528 B):
//   [0, 65536)        u64 keys[8192]
//   [65536, 81920)    u32 hist[4096]  (alias: u64 bestkey[1024])
//   [81920, 86016)    int part[1024]
//   [86016, 86528)    u8  avail[512]
__global__ __launch_bounds__(1024) void k6_points(float* __restrict__ out){
    extern __shared__ unsigned char sraw[];
    unsigned long long* keys = (unsigned long long*)sraw;
    unsigned int* hist = (unsigned int*)(sraw + 65536);
    unsigned long long* bestkey = (unsigned long long*)(sraw + 65536);
    int* part = (int*)(sraw + 81920);
    unsigned char* avail = (unsigned char*)(sraw + 86016);
    __shared__ int s_ti[KP];
    __shared__ int sT, sTf, sM, sChi, sCnt, sPick, sCur;
    __shared__ int chosenIdx[NPTS];
    __shared__ int fbIdx[NPTS];
    __shared__ unsigned long long sWin;

    int b = blockIdx.x, tid = threadIdx.x;
    int N = g_cand_cnt[b];
    if (N > NPIX) N = NPIX;
    int need = min(KP, N);
    const float* cv = g_cand_val + (size_t)b*NPIX;
    const int*   ci = g_cand_idx + (size_t)b*NPIX;

    // ---- coarse histogram ----
    hist[tid] = 0u; hist[tid+1024] = 0u; hist[tid+2048] = 0u; hist[tid+3072] = 0u;
    if (tid == 0){ sT = 0; sM = 0; sChi = 0; sTf = 0; }
    __syncthreads();
    for (int i = tid; i < N; i += 1024){
        int bin = max(0, min(4095, (int)(cv[i]*4096.0f)));
        atomicAdd(&hist[bin], 1u);
    }
    __syncthreads();
    int t4 = tid*4;
    {
        int h0 = hist[t4], h1 = hist[t4+1], h2 = hist[t4+2], h3 = hist[t4+3];
        part[tid] = h0+h1+h2+h3;
        __syncthreads();
        for (int d = 1; d < 1024; d <<= 1){
            int v = (tid + d < 1024) ? part[tid + d] : 0;
            __syncthreads();
            part[tid] += v;
            __syncthreads();
        }
        int base = part[tid];
        int s1 = base - h0, s2 = s1 - h1, s3 = s2 - h2;
        int bestT = -1;
        if (s3 >= need) bestT = t4+3;
        else if (s2 >= need) bestT = t4+2;
        else if (s1 >= need) bestT = t4+1;
        else if (base >= need) bestT = t4;
        if (bestT >= 0) atomicMax(&sT, bestT);
    }
    __syncthreads();
    int T = sT;
    // ---- count strictly above bin T, and fine histogram within bin T ----
    hist[tid] = 0u; hist[tid+1024] = 0u; hist[tid+2048] = 0u; hist[tid+3072] = 0u;
    __syncthreads();
    for (int i = tid; i < N; i += 1024){
        float v = cv[i];
        int bin = max(0, min(4095, (int)(v*4096.0f)));
        if (bin > T) atomicAdd(&sChi, 1);
        else if (bin == T){
            float frac = v*4096.0f - (float)T;
            int fb = max(0, min(4095, (int)(frac*4096.0f)));
            atomicAdd(&hist[fb], 1u);
        }
    }
    __syncthreads();
    int needF = need - sChi;   // > 0 by construction of T
    {
        int h0 = hist[t4], h1 = hist[t4+1], h2 = hist[t4+2], h3 = hist[t4+3];
        part[tid] = h0+h1+h2+h3;
        __syncthreads();
        for (int d = 1; d < 1024; d <<= 1){
            int v = (tid + d < 1024) ? part[tid + d] : 0;
            __syncthreads();
            part[tid] += v;
            __syncthreads();
        }
        int base = part[tid];
        int s1 = base - h0, s2 = s1 - h1, s3 = s2 - h2;
        int bestT = -1;
        if (s3 >= needF) bestT = t4+3;
        else if (s2 >= needF) bestT = t4+2;
        else if (s1 >= needF) bestT = t4+1;
        else if (base >= needF) bestT = t4;
        if (bestT >= 0) atomicMax(&sTf, bestT);
    }
    __syncthreads();
    int Tf = sTf;
    // ---- compact survivors ----
    for (int i = tid; i < N; i += 1024){
        float v = cv[i];
        int bin = max(0, min(4095, (int)(v*4096.0f)));
        bool take = (bin > T);
        if (!take && bin == T){
            float frac = v*4096.0f - (float)T;
            int fb = max(0, min(4095, (int)(frac*4096.0f)));
            take = (fb >= Tf);
        }
        if (take){
            int p = atomicAdd(&sM, 1);
            if (p < SORTN)
                keys[p] = ((unsigned long long)__float_as_uint(v) << 32)
                        | (unsigned int)(~(unsigned)ci[i]);
        }
    }
    __syncthreads();
    int M = min(sM, SORTN);
    int S = 512;
    while (S < M) S <<= 1;
    for (int i = M + tid; i < S; i += 1024) keys[i] = 0ULL;
    __syncthreads();
    for (int k = 2; k <= S; k <<= 1){
        for (int j = k >> 1; j > 0; j >>= 1){
            for (int i = tid; i < S; i += 1024){
                int ixj = i ^ j;
                if (ixj > i){
                    unsigned long long a = keys[i], c = keys[ixj];
                    bool up = ((i & k) == 0);
                    if ((a > c) == up){ keys[i] = c; keys[ixj] = a; }
                }
            }
            __syncthreads();
        }
    }
    if (tid < KP){
        s_ti[tid] = (int)(~(unsigned)(keys[S-1-tid] & 0xffffffffu));
        avail[tid] = 1;
    }
    __syncthreads();

    // ---- greedy NMS first ----
    int Kv = min(N, KP);
    if (tid == 0){ sCnt = 0; sCur = 0; }
    __syncthreads();
    for (int round = 0; round < NPTS; round++){
        if (tid == 0){
            int i = sCur;
            while (i < Kv && !avail[i]) i++;
            if (i < Kv){
                chosenIdx[sCnt] = s_ti[i];
                sCnt++;
                sPick = i;
                sCur = i + 1;
            } else sPick = -1;
        }
        __syncthreads();
        int i = sPick;
        if (i < 0) break;
        int idx = s_ti[i];
        int xi = idx & (HS-1), yi = idx >> 9;
        if (tid < KP && tid > i && tid < Kv && avail[tid]){
            int dx = (s_ti[tid] & (HS-1)) - xi;
            int dy = (s_ti[tid] >> 9) - yi;
            if (dx*dx + dy*dy < 625) avail[tid] = 0;
        }
        __syncthreads();
    }
    int cnt = sCnt;

    // ---- fallback top-10 (non-peak pixels) ONLY if NMS came up short ----
    if (cnt < NPTS){
        const float* s = g_sal + (size_t)b*NPIX;
        float lv[NPTS]; int li[NPTS];
        #pragma unroll
        for (int k=0;k<NPTS;k++){ lv[k] = -1e30f; li[k] = 0x7fffffff; }
        for (int p = tid; p < NPIX; p += 1024){
            float v = s[p];
            if (v <= lv[NPTS-1]) continue;
            int y = p >> 9, x = p & (HS-1);
            float mp = v;
            #pragma unroll
            for (int dy=-1; dy<=1; dy++){
                int yy = y + dy; if (yy < 0 || yy >= HS) continue;
                #pragma unroll
                for (int dx=-1; dx<=1; dx++){
                    int xx = x + dx; if (xx < 0 || xx >= HS) continue;
                    mp = fmaxf(mp, s[yy*HS + xx]);
                }
            }
            if (v == mp) continue;
            float cvv = v; int cix = p;
            #pragma unroll
            for (int k=0;k<NPTS;k++){
                bool better = (cvv > lv[k]) || (cvv == lv[k] && cix < li[k]);
                float tv = lv[k]; int ti = li[k];
                if (better){ lv[k] = cvv; li[k] = cix; cvv = tv; cix = ti; }
            }
        }
        int ptr = 0;
        for (int r = 0; r < NPTS; r++){
            unsigned long long mykey = 0ULL;
            if (ptr < NPTS && lv[ptr] > -1e29f)
                mykey = ((unsigned long long)__float_as_uint(lv[ptr]) << 32)
                      | (unsigned int)(~(unsigned)li[ptr]);
            bestkey[tid] = mykey;
            __syncthreads();
            for (int st = 512; st > 0; st >>= 1){
                if (tid < st){
                    unsigned long long o = bestkey[tid+st];
                    if (o > bestkey[tid]) bestkey[tid] = o;
                }
                __syncthreads();
            }
            unsigned long long win = bestkey[0];
            if (tid == 0){ fbIdx[r] = (int)(~(unsigned)(win & 0xffffffffu)); sWin = win; }
            __syncthreads();
            if (mykey != 0ULL && mykey == sWin) ptr++;
            __syncthreads();
        }
    }

    if (tid < NPTS){
        int si = (tid < cnt) ? chosenIdx[tid] : fbIdx[tid - cnt];
        out[b*20 + tid*2 + 0] = (float)(si & (HS-1)) * (1.0f/512.0f);
        out[b*20 + tid*2 + 1] = (float)(si >> 9)     * (1.0f/512.0f);
        out[BATCH*NPTS*2 + b*NPTS + tid] = 1.0f;
    }
}

// ---------------- K8: boxes ----------------
__global__ __launch_bounds__(1024) void k8_boxes(float* __restrict__ out){
    __shared__ int sred[1024];
    int b = blockIdx.x, tid = threadIdx.x;
    int rf = g_rowflag[b*HW + tid];
    int cf = g_colflag[b*HW + tid];
    int res[4];
    int init[4] = { rf ? tid : HW, rf ? tid : -1, cf ? tid : HW, cf ? tid : -1 };
    #pragma unroll
    for (int w = 0; w < 4; w++){
        sred[tid] = init[w];
        __syncthreads();
        for (int st = 512; st > 0; st >>= 1){
            if (tid < st){
                int o = sred[tid+st];
                sred[tid] = (w == 0 || w == 2) ? min(sred[tid], o) : max(sred[tid], o);
            }
            __syncthreads();
        }
        res[w] = sred[0];
        __syncthreads();
    }
    if (tid == 0){
        float* bx = out + BATCH*NPTS*2 + BATCH*NPTS + b*4;
        if (res[1] >= 0){ bx[0]=(float)res[2]; bx[1]=(float)res[0]; bx[2]=(float)res[3]; bx[3]=(float)res[1]; }
        else            { bx[0]=0.f; bx[1]=0.f; bx[2]=(float)(HW-1); bx[3]=(float)(HW-1); }
    }
}

// ---------------- launch ----------------
extern "C" void kernel_launch(void* const* d_in, const int* in_sizes, int n_in,
                              void* d_out, int out_size){
    (void)in_sizes; (void)n_in; (void)out_size;
    const float* rgb = (const float*)d_in[0];
    const float* dep = (const float*)d_in[1];
    const float* w1  = (const float*)d_in[2];
    const float* b1  = (const float*)d_in[3];
    const float* gam = (const float*)d_in[4];
    const float* bet = (const float*)d_in[5];
    const float* mu  = (const float*)d_in[6];
    const float* var = (const float*)d_in[7];
    const float* w2  = (const float*)d_in[8];
    const float* b2  = (const float*)d_in[9];
    float* out = (float*)d_out;
    float* masks = out + (BATCH*NPTS*2 + BATCH*NPTS + BATCH*4);  // 272

    dim3 blk(32,8);
    k0_zero<<<(BATCH*HW + 255)/256, 256>>>();
    k1_freq<<<dim3(16,64,BATCH), blk>>>(rgb, dep);
    k2_smooth<<<dim3(16,64,BATCH*2), blk>>>();
    cudaFuncSetAttribute(k3_conv, cudaFuncAttributeMaxDynamicSharedMemorySize, K3_SMEM);
    k3_conv<<<dim3(16,16,BATCH), 256, K3_SMEM>>>(w1,b1,gam,bet,mu,var,w2,b2);
    k45_mask_peaks<<<dim3(16,64,BATCH), blk>>>(masks);
    cudaFuncSetAttribute(k6_points, cudaFuncAttributeMaxDynamicSharedMemorySize, 86528);
    k6_points<<<BATCH, 1024, 86528>>>(out);
    k8_boxes<<<BATCH, 1024>>>(out);
}

// round 7
// speedup vs baseline: 3.6801x; 1.1245x over previous
#include <cuda_runtime.h>
#include <math.h>

#define BATCH 8
#define HW 1024
#define HS 512
#define NPIX (HS*HS)
#define NPTS 10
#define KP 512
#define SORTN 8192

// ---------------- scratch (device globals; no allocation) ----------------
__device__ float g_freq[BATCH*12*NPIX];
__device__ float g_sal[BATCH*NPIX];
__device__ float g_cand_val[BATCH*NPIX];
__device__ int   g_cand_idx[BATCH*NPIX];
__device__ int   g_cand_cnt[BATCH];
__device__ int   g_rowflag[BATCH*HW];
__device__ int   g_colflag[BATCH*HW];

// ---------------- packed f32x2 helpers ----------------
__device__ __forceinline__ unsigned long long fma2(unsigned long long a,
                                                   unsigned long long b,
                                                   unsigned long long c){
    unsigned long long d;
    asm("fma.rn.f32x2 %0, %1, %2, %3;" : "=l"(d) : "l"(a), "l"(b), "l"(c));
    return d;
}
__device__ __forceinline__ unsigned long long pack2(float v){
    unsigned long long d;
    asm("mov.b64 %0, {%1, %1};" : "=l"(d) : "f"(v));
    return d;
}
__device__ __forceinline__ void unpack2(unsigned long long p, float& lo, float& hi){
    asm("mov.b64 {%0, %1}, %2;" : "=f"(lo), "=f"(hi) : "l"(p));
}

// ---------------- K0 ----------------
__global__ void k0_zero(){
    int i = blockIdx.x*256 + threadIdx.x;
    if (i < BATCH) g_cand_cnt[i] = 0;
    if (i < BATCH*HW){ g_rowflag[i] = 0; g_colflag[i] = 0; }
}

// ---------------- K1: gray + Haar DWT + energy (freq ch 0..9) ----------------
__global__ void k1_freq(const float* __restrict__ rgb, const float* __restrict__ dep){
    int x = blockIdx.x*32 + threadIdx.x;
    int y = blockIdx.y*8  + threadIdx.y;
    int b = blockIdx.z;
    size_t plane = (size_t)HW*HW;
    const float2* rp = (const float2*)(rgb + (size_t)b*3*plane);
    const float2* gp = rp + plane/2;
    const float2* bp = gp + plane/2;
    const float2* dp = (const float2*)(dep + (size_t)b*plane);
    int r0 = y*HW + x;
    int r1 = r0 + HW/2;
    float2 ra = rp[r0], rb = rp[r1], ga = gp[r0], gb = gp[r1], ba = bp[r0], bb = bp[r1];
    float v00 = (ra.x+ga.x+ba.x)/3.0f;
    float v01 = (ra.y+ga.y+ba.y)/3.0f;
    float v10 = (rb.x+gb.x+bb.x)/3.0f;
    float v11 = (rb.y+gb.y+bb.y)/3.0f;
    int p = y*HS + x;
    float* F = g_freq + (size_t)b*12*NPIX;
    {
        float a=v00*0.5f, c=v10*0.5f, e=v01*0.5f, f=v11*0.5f;
        float LL=a+c, LH=a-c, HL=e+f, HH=e-f;
        F[0*NPIX+p]=LL; F[1*NPIX+p]=LH; F[2*NPIX+p]=HL; F[3*NPIX+p]=HH;
        F[8*NPIX+p]=sqrtf(LH*LH+HL*HL+HH*HH+1e-8f);
    }
    {
        float2 da = dp[r0], db = dp[r1];
        float a=da.x*0.5f, c=db.x*0.5f, e=da.y*0.5f, f=db.y*0.5f;
        float LL=a+c, LH=a-c, HL=e+f, HH=e-f;
        F[4*NPIX+p]=LL; F[5*NPIX+p]=LH; F[6*NPIX+p]=HL; F[7*NPIX+p]=HH;
        F[9*NPIX+p]=sqrtf(LH*LH+HL*HL+HH*HH+1e-8f);
    }
}

// ---------------- K2: separable 5x5 gaussian (-> ch 10,11) ----------------
__global__ void k2_smooth(){
    __shared__ float tile[12][36];
    __shared__ float hbuf[12][32];
    int tx = threadIdx.x, ty = threadIdx.y;
    int tid = ty*32 + tx;
    const float e0 = 1.0f, e1 = 0.60653065971f, e2 = 0.13533528323f;
    const float sum1 = e0 + 2.f*e1 + 2.f*e2;
    const float w0 = e0/sum1, w1 = e1/sum1, w2 = e2/sum1;
    int x0 = blockIdx.x*32, y0 = blockIdx.y*8;
    int b = blockIdx.z >> 1, e = blockIdx.z & 1;
    const float* src = g_freq + ((size_t)b*12 + 8 + e)*NPIX;
    for (int l = tid; l < 12*36; l += 256){
        int r = l/36, c = l%36;
        int gy = y0 + r - 2, gx = x0 + c - 2;
        float v = 0.f;
        if (gy >= 0 && gy < HS && gx >= 0 && gx < HS) v = src[gy*HS + gx];
        tile[r][c] = v;
    }
    __syncthreads();
    for (int l = tid; l < 12*32; l += 256){
        int r = l/32, c = l%32;
        hbuf[r][c] = w2*(tile[r][c] + tile[r][c+4]) + w1*(tile[r][c+1] + tile[r][c+3]) + w0*tile[r][c+2];
    }
    __syncthreads();
    float acc = w2*(hbuf[ty][tx] + hbuf[ty+4][tx]) + w1*(hbuf[ty+1][tx] + hbuf[ty+3][tx]) + w0*hbuf[ty+2][tx];
    g_freq[((size_t)b*12 + 10 + e)*NPIX + (y0+ty)*HS + (x0+tx)] = acc;
}

// ---------------- K3: fused conv+BN+GELU+conv1x1+sigmoid, f32x2, 2 px/thread ----------------
__global__ __launch_bounds__(256, 1) void k3_conv(
    const float* __restrict__ w1, const float* __restrict__ b1,
    const float* __restrict__ gam, const float* __restrict__ bet,
    const float* __restrict__ mu,  const float* __restrict__ var,
    const float* __restrict__ w2,  const float* __restrict__ b2)
{
    __shared__ float sIn[12*18*34];
    __shared__ __align__(16) float sW[3456];
    __shared__ float sSc[32], sSh[32], sW2[32];
    __shared__ float sB2;
    int tid = threadIdx.x;
    int b = blockIdx.z;
    int ty0 = blockIdx.y*16, tx0 = blockIdx.x*32;
    const float* F = g_freq + (size_t)b*12*NPIX;
    for (int l = tid; l < 12*612; l += 256){
        int c = l/612, r = l%612, iy = r/34, ix = r%34;
        int gy = ty0 + iy - 1, gx = tx0 + ix - 1;
        float v = 0.f;
        if (gy >= 0 && gy < HS && gx >= 0 && gx < HS) v = F[(size_t)c*NPIX + gy*HS + gx];
        sIn[l] = v;
    }
    for (int l = tid; l < 3456; l += 256){
        int tl = l >> 5, oc = l & 31;
        sW[l] = w1[oc*108 + tl];
    }
    if (tid < 32){
        float inv = 1.0f/sqrtf(var[tid] + 1e-5f);
        float sc = gam[tid]*inv;
        sSc[tid] = sc;
        sSh[tid] = (b1[tid] - mu[tid])*sc + bet[tid];
        sW2[tid] = w2[tid];
    }
    if (tid == 0) sB2 = b2[0];
    __syncthreads();
    int ty = tid >> 5, tx = tid & 31;
    unsigned long long accA[16], accB[16];
    #pragma unroll
    for (int i=0;i<16;i++){ accA[i] = 0ULL; accB[i] = 0ULL; }
    const ulonglong2* sWu = reinterpret_cast<const ulonglong2*>(sW);
    for (int c=0; c<12; c++){
        #pragma unroll
        for (int tap=0; tap<9; tap++){
            int ky = tap/3, kx = tap%3;
            float a0 = sIn[c*612 + (ty+ky)*34 + (tx+kx)];
            float a1 = sIn[c*612 + (ty+8+ky)*34 + (tx+kx)];
            unsigned long long v0 = pack2(a0), v1 = pack2(a1);
            const ulonglong2* wrow = sWu + (c*9+tap)*8;
            #pragma unroll
            for (int q=0;q<8;q++){
                ulonglong2 wp = wrow[q];
                accA[2*q+0] = fma2(v0, wp.x, accA[2*q+0]);
                accA[2*q+1] = fma2(v0, wp.y, accA[2*q+1]);
                accB[2*q+0] = fma2(v1, wp.x, accB[2*q+0]);
                accB[2*q+1] = fma2(v1, wp.y, accB[2*q+1]);
            }
        }
    }
    float zA = sB2, zB = sB2;
    #pragma unroll
    for (int j=0; j<16; j++){
        float a0, a1, b0, b1v;
        unpack2(accA[j], a0, a1);
        unpack2(accB[j], b0, b1v);
        int oc = 2*j;
        {
            float xv = fmaf(a0, sSc[oc], sSh[oc]);
            float gl = 0.5f*xv*(1.0f + tanhf(0.7978845608f*(xv + 0.044715f*xv*xv*xv)));
            zA = fmaf(gl, sW2[oc], zA);
        }
        {
            float xv = fmaf(a1, sSc[oc+1], sSh[oc+1]);
            float gl = 0.5f*xv*(1.0f + tanhf(0.7978845608f*(xv + 0.044715f*xv*xv*xv)));
            zA = fmaf(gl, sW2[oc+1], zA);
        }
        {
            float xv = fmaf(b0, sSc[oc], sSh[oc]);
            float gl = 0.5f*xv*(1.0f + tanhf(0.7978845608f*(xv + 0.044715f*xv*xv*xv)));
            zB = fmaf(gl, sW2[oc], zB);
        }
        {
            float xv = fmaf(b1v, sSc[oc+1], sSh[oc+1]);
            float gl = 0.5f*xv*(1.0f + tanhf(0.7978845608f*(xv + 0.044715f*xv*xv*xv)));
            zB = fmaf(gl, sW2[oc+1], zB);
        }
    }
    float* S = g_sal + (size_t)b*NPIX;
    S[(ty0+ty)*HS + (tx0+tx)]     = 1.0f/(1.0f + expf(-zA));
    S[(ty0+ty+8)*HS + (tx0+tx)]   = 1.0f/(1.0f + expf(-zB));
}

// ---------------- K45: fused bilinear x2 upsample + flags + peaks ----------------
__global__ void k45_mask_peaks(float* __restrict__ masks){
    __shared__ int colAny[64];
    __shared__ int rowAny[16];
    __shared__ float sv[256];
    __shared__ int   si[256];
    __shared__ int   scnt, sbase;
    int tx = threadIdx.x, ty = threadIdx.y;
    int tid = ty*32 + tx;
    if (tid < 64) colAny[tid] = 0;
    if (tid < 16) rowAny[tid] = 0;
    if (tid == 0) scnt = 0;
    __syncthreads();
    int x = blockIdx.x*32 + tx;
    int y = blockIdx.y*8  + ty;
    int b = blockIdx.z;
    const float* s = g_sal + (size_t)b*NPIX;
    int xm = max(x-1,0), xp = min(x+1,HS-1);
    int ym = max(y-1,0), yp = min(y+1,HS-1);
    float n00=s[ym*HS+xm], n01=s[ym*HS+x], n02=s[ym*HS+xp];
    float n10=s[y*HS+xm],  v  =s[y*HS+x],  n12=s[y*HS+xp];
    float n20=s[yp*HS+xm], n21=s[yp*HS+x], n22=s[yp*HS+xp];
    float mp = fmaxf(fmaxf(fmaxf(n00,n01),fmaxf(n02,n10)),
                     fmaxf(fmaxf(v,n12),fmaxf(fmaxf(n20,n21),n22)));
    bool pk = (v == mp) && (v > 0.f);
    if (pk){
        int p = atomicAdd(&scnt, 1);
        sv[p] = v; si[p] = y*HS + x;
    }
    float m00 = 0.25f*(0.25f*n00 + 0.75f*n01) + 0.75f*(0.25f*n10 + 0.75f*v);
    float m01 = 0.25f*(0.75f*n01 + 0.25f*n02) + 0.75f*(0.75f*v + 0.25f*n12);
    float m10 = 0.75f*(0.25f*n10 + 0.75f*v)   + 0.25f*(0.25f*n20 + 0.75f*n21);
    float m11 = 0.75f*(0.75f*v + 0.25f*n12)   + 0.25f*(0.75f*n21 + 0.25f*n22);
    float* M = masks + (size_t)b*HW*HW;
    *(float2*)&M[(size_t)(2*y)*HW   + 2*x] = make_float2(m00, m01);
    *(float2*)&M[(size_t)(2*y+1)*HW + 2*x] = make_float2(m10, m11);
    bool r0 = (m00 > 0.5f) || (m01 > 0.5f);
    bool r1 = (m10 > 0.5f) || (m11 > 0.5f);
    bool c0 = (m00 > 0.5f) || (m10 > 0.5f);
    bool c1 = (m01 > 0.5f) || (m11 > 0.5f);
    if (r0) rowAny[2*ty] = 1;
    if (r1) rowAny[2*ty+1] = 1;
    if (c0) colAny[2*tx] = 1;
    if (c1) colAny[2*tx+1] = 1;
    __syncthreads();
    if (tid < 16 && rowAny[tid]) atomicOr(&g_rowflag[b*HW + blockIdx.y*16 + tid], 1);
    if (tid < 64 && colAny[tid]) atomicOr(&g_colflag[b*HW + blockIdx.x*64 + tid], 1);
    if (tid == 0 && scnt) sbase = atomicAdd(&g_cand_cnt[b], scnt);
    __syncthreads();
    if (tid < scnt){
        g_cand_val[(size_t)b*NPIX + sbase + tid] = sv[tid];
        g_cand_idx[(size_t)b*NPIX + sbase + tid] = si[tid];
    }
}

// ---------------- K6: two-level select + sort + NMS + conditional fallback ----------------
__global__ __launch_bounds__(1024) void k6_points(float* __restrict__ out){
    extern __shared__ unsigned char sraw[];
    unsigned long long* keys = (unsigned long long*)sraw;
    unsigned int* hist = (unsigned int*)(sraw + 65536);
    unsigned long long* bestkey = (unsigned long long*)(sraw + 65536);
    int* part = (int*)(sraw + 81920);
    unsigned char* avail = (unsigned char*)(sraw + 86016);
    __shared__ int s_ti[KP];
    __shared__ int sT, sTf, sM, sChi, sCnt, sPick, sCur;
    __shared__ int chosenIdx[NPTS];
    __shared__ int fbIdx[NPTS];
    __shared__ unsigned long long sWin;

    int b = blockIdx.x, tid = threadIdx.x;
    int N = g_cand_cnt[b];
    if (N > NPIX) N = NPIX;
    int need = min(KP, N);
    const float* cv = g_cand_val + (size_t)b*NPIX;
    const int*   ci = g_cand_idx + (size_t)b*NPIX;

    hist[tid] = 0u; hist[tid+1024] = 0u; hist[tid+2048] = 0u; hist[tid+3072] = 0u;
    if (tid == 0){ sT = 0; sM = 0; sChi = 0; sTf = 0; }
    __syncthreads();
    for (int i = tid; i < N; i += 1024){
        int bin = max(0, min(4095, (int)(cv[i]*4096.0f)));
        atomicAdd(&hist[bin], 1u);
    }
    __syncthreads();
    int t4 = tid*4;
    {
        int h0 = hist[t4], h1 = hist[t4+1], h2 = hist[t4+2], h3 = hist[t4+3];
        part[tid] = h0+h1+h2+h3;
        __syncthreads();
        for (int d = 1; d < 1024; d <<= 1){
            int v = (tid + d < 1024) ? part[tid + d] : 0;
            __syncthreads();
            part[tid] += v;
            __syncthreads();
        }
        int base = part[tid];
        int s1 = base - h0, s2 = s1 - h1, s3 = s2 - h2;
        int bestT = -1;
        if (s3 >= need) bestT = t4+3;
        else if (s2 >= need) bestT = t4+2;
        else if (s1 >= need) bestT = t4+1;
        else if (base >= need) bestT = t4;
        if (bestT >= 0) atomicMax(&sT, bestT);
    }
    __syncthreads();
    int T = sT;
    hist[tid] = 0u; hist[tid+1024] = 0u; hist[tid+2048] = 0u; hist[tid+3072] = 0u;
    __syncthreads();
    for (int i = tid; i < N; i += 1024){
        float v = cv[i];
        int bin = max(0, min(4095, (int)(v*4096.0f)));
        if (bin > T) atomicAdd(&sChi, 1);
        else if (bin == T){
            float frac = v*4096.0f - (float)T;
            int fb = max(0, min(4095, (int)(frac*4096.0f)));
            atomicAdd(&hist[fb], 1u);
        }
    }
    __syncthreads();
    int needF = need - sChi;
    {
        int h0 = hist[t4], h1 = hist[t4+1], h2 = hist[t4+2], h3 = hist[t4+3];
        part[tid] = h0+h1+h2+h3;
        __syncthreads();
        for (int d = 1; d < 1024; d <<= 1){
            int v = (tid + d < 1024) ? part[tid + d] : 0;
            __syncthreads();
            part[tid] += v;
            __syncthreads();
        }
        int base = part[tid];
        int s1 = base - h0, s2 = s1 - h1, s3 = s2 - h2;
        int bestT = -1;
        if (s3 >= needF) bestT = t4+3;
        else if (s2 >= needF) bestT = t4+2;
        else if (s1 >= needF) bestT = t4+1;
        else if (base >= needF) bestT = t4;
        if (bestT >= 0) atomicMax(&sTf, bestT);
    }
    __syncthreads();
    int Tf = sTf;
    for (int i = tid; i < N; i += 1024){
        float v = cv[i];
        int bin = max(0, min(4095, (int)(v*4096.0f)));
        bool take = (bin > T);
        if (!take && bin == T){
            float frac = v*4096.0f - (float)T;
            int fb = max(0, min(4095, (int)(frac*4096.0f)));
            take = (fb >= Tf);
        }
        if (take){
            int p = atomicAdd(&sM, 1);
            if (p < SORTN)
                keys[p] = ((unsigned long long)__float_as_uint(v) << 32)
                        | (unsigned int)(~(unsigned)ci[i]);
        }
    }
    __syncthreads();
    int M = min(sM, SORTN);
    int S = 512;
    while (S < M) S <<= 1;
    for (int i = M + tid; i < S; i += 1024) keys[i] = 0ULL;
    __syncthreads();
    for (int k = 2; k <= S; k <<= 1){
        for (int j = k >> 1; j > 0; j >>= 1){
            for (int i = tid; i < S; i += 1024){
                int ixj = i ^ j;
                if (ixj > i){
                    unsigned long long a = keys[i], c = keys[ixj];
                    bool up = ((i & k) == 0);
                    if ((a > c) == up){ keys[i] = c; keys[ixj] = a; }
                }
            }
            __syncthreads();
        }
    }
    if (tid < KP){
        s_ti[tid] = (int)(~(unsigned)(keys[S-1-tid] & 0xffffffffu));
        avail[tid] = 1;
    }
    __syncthreads();

    int Kv = min(N, KP);
    if (tid == 0){ sCnt = 0; sCur = 0; }
    __syncthreads();
    for (int round = 0; round < NPTS; round++){
        if (tid == 0){
            int i = sCur;
            while (i < Kv && !avail[i]) i++;
            if (i < Kv){
                chosenIdx[sCnt] = s_ti[i];
                sCnt++;
                sPick = i;
                sCur = i + 1;
            } else sPick = -1;
        }
        __syncthreads();
        int i = sPick;
        if (i < 0) break;
        int idx = s_ti[i];
        int xi = idx & (HS-1), yi = idx >> 9;
        if (tid < KP && tid > i && tid < Kv && avail[tid]){
            int dx = (s_ti[tid] & (HS-1)) - xi;
            int dy = (s_ti[tid] >> 9) - yi;
            if (dx*dx + dy*dy < 625) avail[tid] = 0;
        }
        __syncthreads();
    }
    int cnt = sCnt;

    if (cnt < NPTS){
        const float* s = g_sal + (size_t)b*NPIX;
        float lv[NPTS]; int li[NPTS];
        #pragma unroll
        for (int k=0;k<NPTS;k++){ lv[k] = -1e30f; li[k] = 0x7fffffff; }
        for (int p = tid; p < NPIX; p += 1024){
            float v = s[p];
            if (v <= lv[NPTS-1]) continue;
            int y = p >> 9, x = p & (HS-1);
            float mp = v;
            #pragma unroll
            for (int dy=-1; dy<=1; dy++){
                int yy = y + dy; if (yy < 0 || yy >= HS) continue;
                #pragma unroll
                for (int dx=-1; dx<=1; dx++){
                    int xx = x + dx; if (xx < 0 || xx >= HS) continue;
                    mp = fmaxf(mp, s[yy*HS + xx]);
                }
            }
            if (v == mp) continue;
            float cvv = v; int cix = p;
            #pragma unroll
            for (int k=0;k<NPTS;k++){
                bool better = (cvv > lv[k]) || (cvv == lv[k] && cix < li[k]);
                float tv = lv[k]; int ti = li[k];
                if (better){ lv[k] = cvv; li[k] = cix; cvv = tv; cix = ti; }
            }
        }
        int ptr = 0;
        for (int r = 0; r < NPTS; r++){
            unsigned long long mykey = 0ULL;
            if (ptr < NPTS && lv[ptr] > -1e29f)
                mykey = ((unsigned long long)__float_as_uint(lv[ptr]) << 32)
                      | (unsigned int)(~(unsigned)li[ptr]);
            bestkey[tid] = mykey;
            __syncthreads();
            for (int st = 512; st > 0; st >>= 1){
                if (tid < st){
                    unsigned long long o = bestkey[tid+st];
                    if (o > bestkey[tid]) bestkey[tid] = o;
                }
                __syncthreads();
            }
            unsigned long long win = bestkey[0];
            if (tid == 0){ fbIdx[r] = (int)(~(unsigned)(win & 0xffffffffu)); sWin = win; }
            __syncthreads();
            if (mykey != 0ULL && mykey == sWin) ptr++;
            __syncthreads();
        }
    }

    if (tid < NPTS){
        int si = (tid < cnt) ? chosenIdx[tid] : fbIdx[tid - cnt];
        out[b*20 + tid*2 + 0] = (float)(si & (HS-1)) * (1.0f/512.0f);
        out[b*20 + tid*2 + 1] = (float)(si >> 9)     * (1.0f/512.0f);
        out[BATCH*NPTS*2 + b*NPTS + tid] = 1.0f;
    }
}

// ---------------- K8: boxes ----------------
__global__ __launch_bounds__(1024) void k8_boxes(float* __restrict__ out){
    __shared__ int sred[1024];
    int b = blockIdx.x, tid = threadIdx.x;
    int rf = g_rowflag[b*HW + tid];
    int cf = g_colflag[b*HW + tid];
    int res[4];
    int init[4] = { rf ? tid : HW, rf ? tid : -1, cf ? tid : HW, cf ? tid : -1 };
    #pragma unroll
    for (int w = 0; w < 4; w++){
        sred[tid] = init[w];
        __syncthreads();
        for (int st = 512; st > 0; st >>= 1){
            if (tid < st){
                int o = sred[tid+st];
                sred[tid] = (w == 0 || w == 2) ? min(sred[tid], o) : max(sred[tid], o);
            }
            __syncthreads();
        }
        res[w] = sred[0];
        __syncthreads();
    }
    if (tid == 0){
        float* bx = out + BATCH*NPTS*2 + BATCH*NPTS + b*4;
        if (res[1] >= 0){ bx[0]=(float)res[2]; bx[1]=(float)res[0]; bx[2]=(float)res[3]; bx[3]=(float)res[1]; }
        else            { bx[0]=0.f; bx[1]=0.f; bx[2]=(float)(HW-1); bx[3]=(float)(HW-1); }
    }
}

// ---------------- launch ----------------
extern "C" void kernel_launch(void* const* d_in, const int* in_sizes, int n_in,
                              void* d_out, int out_size){
    (void)in_sizes; (void)n_in; (void)out_size;
    const float* rgb = (const float*)d_in[0];
    const float* dep = (const float*)d_in[1];
    const float* w1  = (const float*)d_in[2];
    const float* b1  = (const float*)d_in[3];
    const float* gam = (const float*)d_in[4];
    const float* bet = (const float*)d_in[5];
    const float* mu  = (const float*)d_in[6];
    const float* var = (const float*)d_in[7];
    const float* w2  = (const float*)d_in[8];
    const float* b2  = (const float*)d_in[9];
    float* out = (float*)d_out;
    float* masks = out + (BATCH*NPTS*2 + BATCH*NPTS + BATCH*4);  // 272

    dim3 blk(32,8);
    k0_zero<<<(BATCH*HW + 255)/256, 256>>>();
    k1_freq<<<dim3(16,64,BATCH), blk>>>(rgb, dep);
    k2_smooth<<<dim3(16,64,BATCH*2), blk>>>();
    k3_conv<<<dim3(16,32,BATCH), 256>>>(w1,b1,gam,bet,mu,var,w2,b2);
    k45_mask_peaks<<<dim3(16,64,BATCH), blk>>>(masks);
    cudaFuncSetAttribute(k6_points, cudaFuncAttributeMaxDynamicSharedMemorySize, 86528);
    k6_points<<<BATCH, 1024, 86528>>>(out);
    k8_boxes<<<BATCH, 1024>>>(out);
}

// round 8
// speedup vs baseline: 4.6056x; 1.2515x over previous
#include <cuda_runtime.h>
#include <math.h>

#define BATCH 8
#define HW 1024
#define HS 512
#define NPIX (HS*HS)
#define NPTS 10
#define KP 512
#define SORTN 8192

// ---------------- scratch (device globals; no allocation) ----------------
__device__ float g_freq[BATCH*12*NPIX];
__device__ float g_sal[BATCH*NPIX];
__device__ float g_cand_val[BATCH*NPIX];
__device__ int   g_cand_idx[BATCH*NPIX];
__device__ int   g_cand_cnt[BATCH];
__device__ int   g_rowflag[BATCH*HW];
__device__ int   g_colflag[BATCH*HW];

// reordered conv1 weights: [(c*9+tap)*8 + q] = ulonglong2{oc 4q..4q+1, oc 4q+2..4q+3}
__device__ __align__(16) float g_wre[3456];
__constant__ __align__(16) ulonglong2 cW[864];

// ---------------- packed f32x2 helpers ----------------
__device__ __forceinline__ unsigned long long fma2(unsigned long long a,
                                                   unsigned long long b,
                                                   unsigned long long c){
    unsigned long long d;
    asm("fma.rn.f32x2 %0, %1, %2, %3;" : "=l"(d) : "l"(a), "l"(b), "l"(c));
    return d;
}
__device__ __forceinline__ unsigned long long pack2(float v){
    unsigned long long d;
    asm("mov.b64 %0, {%1, %1};" : "=l"(d) : "f"(v));
    return d;
}
__device__ __forceinline__ void unpack2(unsigned long long p, float& lo, float& hi){
    asm("mov.b64 {%0, %1}, %2;" : "=f"(lo), "=f"(hi) : "l"(p));
}

// ---------------- KW: reorder conv1 weights for constant bank ----------------
__global__ void kw_reorder(const float* __restrict__ w1){
    int l = blockIdx.x*256 + threadIdx.x;
    if (l >= 3456) return;
    int tl = l >> 5, oc = l & 31;
    g_wre[tl*32 + oc] = w1[oc*108 + tl];
}

// ---------------- K1: gray + Haar DWT + energy (freq ch 0..9) + zero flags ----------------
__global__ void k1_freq(const float* __restrict__ rgb, const float* __restrict__ dep){
    int x = blockIdx.x*32 + threadIdx.x;
    int y = blockIdx.y*8  + threadIdx.y;
    int b = blockIdx.z;
    // fold former k0: zero counters/flags (consumed by k45, 3 kernels later)
    if (blockIdx.x == 0 && blockIdx.y < 4){
        int l = (b*4 + blockIdx.y)*256 + threadIdx.y*32 + threadIdx.x;  // 0..8191
        g_rowflag[l] = 0; g_colflag[l] = 0;
        if (l < BATCH) g_cand_cnt[l] = 0;
    }
    size_t plane = (size_t)HW*HW;
    const float2* rp = (const float2*)(rgb + (size_t)b*3*plane);
    const float2* gp = rp + plane/2;
    const float2* bp = gp + plane/2;
    const float2* dp = (const float2*)(dep + (size_t)b*plane);
    int r0 = y*HW + x;
    int r1 = r0 + HW/2;
    float2 ra = rp[r0], rb = rp[r1], ga = gp[r0], gb = gp[r1], ba = bp[r0], bb = bp[r1];
    float v00 = (ra.x+ga.x+ba.x)/3.0f;
    float v01 = (ra.y+ga.y+ba.y)/3.0f;
    float v10 = (rb.x+gb.x+bb.x)/3.0f;
    float v11 = (rb.y+gb.y+bb.y)/3.0f;
    int p = y*HS + x;
    float* F = g_freq + (size_t)b*12*NPIX;
    {
        float a=v00*0.5f, c=v10*0.5f, e=v01*0.5f, f=v11*0.5f;
        float LL=a+c, LH=a-c, HL=e+f, HH=e-f;
        F[0*NPIX+p]=LL; F[1*NPIX+p]=LH; F[2*NPIX+p]=HL; F[3*NPIX+p]=HH;
        F[8*NPIX+p]=sqrtf(LH*LH+HL*HL+HH*HH+1e-8f);
    }
    {
        float2 da = dp[r0], db = dp[r1];
        float a=da.x*0.5f, c=db.x*0.5f, e=da.y*0.5f, f=db.y*0.5f;
        float LL=a+c, LH=a-c, HL=e+f, HH=e-f;
        F[4*NPIX+p]=LL; F[5*NPIX+p]=LH; F[6*NPIX+p]=HL; F[7*NPIX+p]=HH;
        F[9*NPIX+p]=sqrtf(LH*LH+HL*HL+HH*HH+1e-8f);
    }
}

// ---------------- K2: separable 5x5 gaussian (-> ch 10,11) ----------------
__global__ void k2_smooth(){
    __shared__ float tile[12][36];
    __shared__ float hbuf[12][32];
    int tx = threadIdx.x, ty = threadIdx.y;
    int tid = ty*32 + tx;
    const float e0 = 1.0f, e1 = 0.60653065971f, e2 = 0.13533528323f;
    const float sum1 = e0 + 2.f*e1 + 2.f*e2;
    const float w0 = e0/sum1, w1 = e1/sum1, w2 = e2/sum1;
    int x0 = blockIdx.x*32, y0 = blockIdx.y*8;
    int b = blockIdx.z >> 1, e = blockIdx.z & 1;
    const float* src = g_freq + ((size_t)b*12 + 8 + e)*NPIX;
    for (int l = tid; l < 12*36; l += 256){
        int r = l/36, c = l%36;
        int gy = y0 + r - 2, gx = x0 + c - 2;
        float v = 0.f;
        if (gy >= 0 && gy < HS && gx >= 0 && gx < HS) v = src[gy*HS + gx];
        tile[r][c] = v;
    }
    __syncthreads();
    for (int l = tid; l < 12*32; l += 256){
        int r = l/32, c = l%32;
        hbuf[r][c] = w2*(tile[r][c] + tile[r][c+4]) + w1*(tile[r][c+1] + tile[r][c+3]) + w0*tile[r][c+2];
    }
    __syncthreads();
    float acc = w2*(hbuf[ty][tx] + hbuf[ty+4][tx]) + w1*(hbuf[ty+1][tx] + hbuf[ty+3][tx]) + w0*hbuf[ty+2][tx];
    g_freq[((size_t)b*12 + 10 + e)*NPIX + (y0+ty)*HS + (x0+tx)] = acc;
}

// ---------------- K3: fused conv+BN+GELU+conv1x1+sigmoid, f32x2, weights in constant ----------------
__global__ __launch_bounds__(256, 1) void k3_conv(
    const float* __restrict__ b1,
    const float* __restrict__ gam, const float* __restrict__ bet,
    const float* __restrict__ mu,  const float* __restrict__ var,
    const float* __restrict__ w2,  const float* __restrict__ b2)
{
    __shared__ float sIn[12*18*34];
    __shared__ float sSc[32], sSh[32], sW2[32];
    __shared__ float sB2;
    int tid = threadIdx.x;
    int b = blockIdx.z;
    int ty0 = blockIdx.y*16, tx0 = blockIdx.x*32;
    const float* F = g_freq + (size_t)b*12*NPIX;
    for (int l = tid; l < 12*612; l += 256){
        int c = l/612, r = l%612, iy = r/34, ix = r%34;
        int gy = ty0 + iy - 1, gx = tx0 + ix - 1;
        float v = 0.f;
        if (gy >= 0 && gy < HS && gx >= 0 && gx < HS) v = F[(size_t)c*NPIX + gy*HS + gx];
        sIn[l] = v;
    }
    if (tid < 32){
        float inv = 1.0f/sqrtf(var[tid] + 1e-5f);
        float sc = gam[tid]*inv;
        sSc[tid] = sc;
        sSh[tid] = (b1[tid] - mu[tid])*sc + bet[tid];
        sW2[tid] = w2[tid];
    }
    if (tid == 0) sB2 = b2[0];
    __syncthreads();
    int ty = tid >> 5, tx = tid & 31;
    unsigned long long accA[16], accB[16];
    #pragma unroll
    for (int i=0;i<16;i++){ accA[i] = 0ULL; accB[i] = 0ULL; }
    for (int c=0; c<12; c++){
        #pragma unroll
        for (int tap=0; tap<9; tap++){
            int ky = tap/3, kx = tap%3;
            float a0 = sIn[c*612 + (ty+ky)*34 + (tx+kx)];
            float a1 = sIn[c*612 + (ty+8+ky)*34 + (tx+kx)];
            unsigned long long v0 = pack2(a0), v1 = pack2(a1);
            const ulonglong2* wrow = cW + (c*9+tap)*8;   // warp-uniform constant reads
            #pragma unroll
            for (int q=0;q<8;q++){
                ulonglong2 wp = wrow[q];
                accA[2*q+0] = fma2(v0, wp.x, accA[2*q+0]);
                accA[2*q+1] = fma2(v0, wp.y, accA[2*q+1]);
                accB[2*q+0] = fma2(v1, wp.x, accB[2*q+0]);
                accB[2*q+1] = fma2(v1, wp.y, accB[2*q+1]);
            }
        }
    }
    float zA = sB2, zB = sB2;
    #pragma unroll
    for (int j=0; j<16; j++){
        float a0, a1, b0, b1v;
        unpack2(accA[j], a0, a1);
        unpack2(accB[j], b0, b1v);
        int oc = 2*j;
        {
            float xv = fmaf(a0, sSc[oc], sSh[oc]);
            float gl = 0.5f*xv*(1.0f + tanhf(0.7978845608f*(xv + 0.044715f*xv*xv*xv)));
            zA = fmaf(gl, sW2[oc], zA);
        }
        {
            float xv = fmaf(a1, sSc[oc+1], sSh[oc+1]);
            float gl = 0.5f*xv*(1.0f + tanhf(0.7978845608f*(xv + 0.044715f*xv*xv*xv)));
            zA = fmaf(gl, sW2[oc+1], zA);
        }
        {
            float xv = fmaf(b0, sSc[oc], sSh[oc]);
            float gl = 0.5f*xv*(1.0f + tanhf(0.7978845608f*(xv + 0.044715f*xv*xv*xv)));
            zB = fmaf(gl, sW2[oc], zB);
        }
        {
            float xv = fmaf(b1v, sSc[oc+1], sSh[oc+1]);
            float gl = 0.5f*xv*(1.0f + tanhf(0.7978845608f*(xv + 0.044715f*xv*xv*xv)));
            zB = fmaf(gl, sW2[oc+1], zB);
        }
    }
    float* S = g_sal + (size_t)b*NPIX;
    S[(ty0+ty)*HS + (tx0+tx)]     = 1.0f/(1.0f + expf(-zA));
    S[(ty0+ty+8)*HS + (tx0+tx)]   = 1.0f/(1.0f + expf(-zB));
}

// ---------------- K45: fused bilinear x2 upsample + flags + peaks ----------------
__global__ void k45_mask_peaks(float* __restrict__ masks){
    __shared__ int colAny[64];
    __shared__ int rowAny[16];
    __shared__ float sv[256];
    __shared__ int   si[256];
    __shared__ int   scnt, sbase;
    int tx = threadIdx.x, ty = threadIdx.y;
    int tid = ty*32 + tx;
    if (tid < 64) colAny[tid] = 0;
    if (tid < 16) rowAny[tid] = 0;
    if (tid == 0) scnt = 0;
    __syncthreads();
    int x = blockIdx.x*32 + tx;
    int y = blockIdx.y*8  + ty;
    int b = blockIdx.z;
    const float* s = g_sal + (size_t)b*NPIX;
    int xm = max(x-1,0), xp = min(x+1,HS-1);
    int ym = max(y-1,0), yp = min(y+1,HS-1);
    float n00=s[ym*HS+xm], n01=s[ym*HS+x], n02=s[ym*HS+xp];
    float n10=s[y*HS+xm],  v  =s[y*HS+x],  n12=s[y*HS+xp];
    float n20=s[yp*HS+xm], n21=s[yp*HS+x], n22=s[yp*HS+xp];
    float mp = fmaxf(fmaxf(fmaxf(n00,n01),fmaxf(n02,n10)),
                     fmaxf(fmaxf(v,n12),fmaxf(fmaxf(n20,n21),n22)));
    bool pk = (v == mp) && (v > 0.f);
    if (pk){
        int p = atomicAdd(&scnt, 1);
        sv[p] = v; si[p] = y*HS + x;
    }
    float m00 = 0.25f*(0.25f*n00 + 0.75f*n01) + 0.75f*(0.25f*n10 + 0.75f*v);
    float m01 = 0.25f*(0.75f*n01 + 0.25f*n02) + 0.75f*(0.75f*v + 0.25f*n12);
    float m10 = 0.75f*(0.25f*n10 + 0.75f*v)   + 0.25f*(0.25f*n20 + 0.75f*n21);
    float m11 = 0.75f*(0.75f*v + 0.25f*n12)   + 0.25f*(0.75f*n21 + 0.25f*n22);
    float* M = masks + (size_t)b*HW*HW;
    *(float2*)&M[(size_t)(2*y)*HW   + 2*x] = make_float2(m00, m01);
    *(float2*)&M[(size_t)(2*y+1)*HW + 2*x] = make_float2(m10, m11);
    bool r0 = (m00 > 0.5f) || (m01 > 0.5f);
    bool r1 = (m10 > 0.5f) || (m11 > 0.5f);
    bool c0 = (m00 > 0.5f) || (m10 > 0.5f);
    bool c1 = (m01 > 0.5f) || (m11 > 0.5f);
    if (r0) rowAny[2*ty] = 1;
    if (r1) rowAny[2*ty+1] = 1;
    if (c0) colAny[2*tx] = 1;
    if (c1) colAny[2*tx+1] = 1;
    __syncthreads();
    if (tid < 16 && rowAny[tid]) atomicOr(&g_rowflag[b*HW + blockIdx.y*16 + tid], 1);
    if (tid < 64 && colAny[tid]) atomicOr(&g_colflag[b*HW + blockIdx.x*64 + tid], 1);
    if (tid == 0 && scnt) sbase = atomicAdd(&g_cand_cnt[b], scnt);
    __syncthreads();
    if (tid < scnt){
        g_cand_val[(size_t)b*NPIX + sbase + tid] = sv[tid];
        g_cand_idx[(size_t)b*NPIX + sbase + tid] = si[tid];
    }
}

// ---------------- K6: points (blocks 0..7) + boxes (blocks 8..15) ----------------
__global__ __launch_bounds__(1024) void k6_points(float* __restrict__ out){
    extern __shared__ unsigned char sraw[];
    int tid = threadIdx.x;

    // ---- boxes half (former k8) ----
    if (blockIdx.x >= BATCH){
        int b = blockIdx.x - BATCH;
        int* sred = (int*)sraw;
        int rf = g_rowflag[b*HW + tid];
        int cf = g_colflag[b*HW + tid];
        int res[4];
        int init[4] = { rf ? tid : HW, rf ? tid : -1, cf ? tid : HW, cf ? tid : -1 };
        #pragma unroll
        for (int w = 0; w < 4; w++){
            sred[tid] = init[w];
            __syncthreads();
            for (int st = 512; st > 0; st >>= 1){
                if (tid < st){
                    int o = sred[tid+st];
                    sred[tid] = (w == 0 || w == 2) ? min(sred[tid], o) : max(sred[tid], o);
                }
                __syncthreads();
            }
            res[w] = sred[0];
            __syncthreads();
        }
        if (tid == 0){
            float* bx = out + BATCH*NPTS*2 + BATCH*NPTS + b*4;
            if (res[1] >= 0){ bx[0]=(float)res[2]; bx[1]=(float)res[0]; bx[2]=(float)res[3]; bx[3]=(float)res[1]; }
            else            { bx[0]=0.f; bx[1]=0.f; bx[2]=(float)(HW-1); bx[3]=(float)(HW-1); }
        }
        return;
    }

    // ---- points half ----
    unsigned long long* keys = (unsigned long long*)sraw;
    unsigned int* hist = (unsigned int*)(sraw + 65536);
    unsigned long long* bestkey = (unsigned long long*)(sraw + 65536);
    int* part = (int*)(sraw + 81920);
    unsigned char* avail = (unsigned char*)(sraw + 86016);
    __shared__ int s_ti[KP];
    __shared__ int sT, sTf, sM, sChi, sCnt, sPick, sCur;
    __shared__ int chosenIdx[NPTS];
    __shared__ int fbIdx[NPTS];
    __shared__ unsigned long long sWin;

    int b = blockIdx.x;
    int N = g_cand_cnt[b];
    if (N > NPIX) N = NPIX;
    int need = min(KP, N);
    const float* cv = g_cand_val + (size_t)b*NPIX;
    const int*   ci = g_cand_idx + (size_t)b*NPIX;

    hist[tid] = 0u; hist[tid+1024] = 0u; hist[tid+2048] = 0u; hist[tid+3072] = 0u;
    if (tid == 0){ sT = 0; sM = 0; sChi = 0; sTf = 0; }
    __syncthreads();
    for (int i = tid; i < N; i += 1024){
        int bin = max(0, min(4095, (int)(cv[i]*4096.0f)));
        atomicAdd(&hist[bin], 1u);
    }
    __syncthreads();
    int t4 = tid*4;
    {
        int h0 = hist[t4], h1 = hist[t4+1], h2 = hist[t4+2], h3 = hist[t4+3];
        part[tid] = h0+h1+h2+h3;
        __syncthreads();
        for (int d = 1; d < 1024; d <<= 1){
            int v = (tid + d < 1024) ? part[tid + d] : 0;
            __syncthreads();
            part[tid] += v;
            __syncthreads();
        }
        int base = part[tid];
        int s1 = base - h0, s2 = s1 - h1, s3 = s2 - h2;
        int bestT = -1;
        if (s3 >= need) bestT = t4+3;
        else if (s2 >= need) bestT = t4+2;
        else if (s1 >= need) bestT = t4+1;
        else if (base >= need) bestT = t4;
        if (bestT >= 0) atomicMax(&sT, bestT);
    }
    __syncthreads();
    int T = sT;
    hist[tid] = 0u; hist[tid+1024] = 0u; hist[tid+2048] = 0u; hist[tid+3072] = 0u;
    __syncthreads();
    for (int i = tid; i < N; i += 1024){
        float v = cv[i];
        int bin = max(0, min(4095, (int)(v*4096.0f)));
        if (bin > T) atomicAdd(&sChi, 1);
        else if (bin == T){
            float frac = v*4096.0f - (float)T;
            int fb = max(0, min(4095, (int)(frac*4096.0f)));
            atomicAdd(&hist[fb], 1u);
        }
    }
    __syncthreads();
    int needF = need - sChi;
    {
        int h0 = hist[t4], h1 = hist[t4+1], h2 = hist[t4+2], h3 = hist[t4+3];
        part[tid] = h0+h1+h2+h3;
        __syncthreads();
        for (int d = 1; d < 1024; d <<= 1){
            int v = (tid + d < 1024) ? part[tid + d] : 0;
            __syncthreads();
            part[tid] += v;
            __syncthreads();
        }
        int base = part[tid];
        int s1 = base - h0, s2 = s1 - h1, s3 = s2 - h2;
        int bestT = -1;
        if (s3 >= needF) bestT = t4+3;
        else if (s2 >= needF) bestT = t4+2;
        else if (s1 >= needF) bestT = t4+1;
        else if (base >= needF) bestT = t4;
        if (bestT >= 0) atomicMax(&sTf, bestT);
    }
    __syncthreads();
    int Tf = sTf;
    for (int i = tid; i < N; i += 1024){
        float v = cv[i];
        int bin = max(0, min(4095, (int)(v*4096.0f)));
        bool take = (bin > T);
        if (!take && bin == T){
            float frac = v*4096.0f - (float)T;
            int fb = max(0, min(4095, (int)(frac*4096.0f)));
            take = (fb >= Tf);
        }
        if (take){
            int p = atomicAdd(&sM, 1);
            if (p < SORTN)
                keys[p] = ((unsigned long long)__float_as_uint(v) << 32)
                        | (unsigned int)(~(unsigned)ci[i]);
        }
    }
    __syncthreads();
    int M = min(sM, SORTN);
    int S = 512;
    while (S < M) S <<= 1;
    for (int i = M + tid; i < S; i += 1024) keys[i] = 0ULL;
    __syncthreads();
    for (int k = 2; k <= S; k <<= 1){
        for (int j = k >> 1; j > 0; j >>= 1){
            for (int i = tid; i < S; i += 1024){
                int ixj = i ^ j;
                if (ixj > i){
                    unsigned long long a = keys[i], c = keys[ixj];
                    bool up = ((i & k) == 0);
                    if ((a > c) == up){ keys[i] = c; keys[ixj] = a; }
                }
            }
            __syncthreads();
        }
    }
    if (tid < KP){
        s_ti[tid] = (int)(~(unsigned)(keys[S-1-tid] & 0xffffffffu));
        avail[tid] = 1;
    }
    __syncthreads();

    int Kv = min(N, KP);
    if (tid == 0){ sCnt = 0; sCur = 0; }
    __syncthreads();
    for (int round = 0; round < NPTS; round++){
        if (tid == 0){
            int i = sCur;
            while (i < Kv && !avail[i]) i++;
            if (i < Kv){
                chosenIdx[sCnt] = s_ti[i];
                sCnt++;
                sPick = i;
                sCur = i + 1;
            } else sPick = -1;
        }
        __syncthreads();
        int i = sPick;
        if (i < 0) break;
        int idx = s_ti[i];
        int xi = idx & (HS-1), yi = idx >> 9;
        if (tid < KP && tid > i && tid < Kv && avail[tid]){
            int dx = (s_ti[tid] & (HS-1)) - xi;
            int dy = (s_ti[tid] >> 9) - yi;
            if (dx*dx + dy*dy < 625) avail[tid] = 0;
        }
        __syncthreads();
    }
    int cnt = sCnt;

    if (cnt < NPTS){
        const float* s = g_sal + (size_t)b*NPIX;
        float lv[NPTS]; int li[NPTS];
        #pragma unroll
        for (int k=0;k<NPTS;k++){ lv[k] = -1e30f; li[k] = 0x7fffffff; }
        for (int p = tid; p < NPIX; p += 1024){
            float v = s[p];
            if (v <= lv[NPTS-1]) continue;
            int y = p >> 9, x = p & (HS-1);
            float mp = v;
            #pragma unroll
            for (int dy=-1; dy<=1; dy++){
                int yy = y + dy; if (yy < 0 || yy >= HS) continue;
                #pragma unroll
                for (int dx=-1; dx<=1; dx++){
                    int xx = x + dx; if (xx < 0 || xx >= HS) continue;
                    mp = fmaxf(mp, s[yy*HS + xx]);
                }
            }
            if (v == mp) continue;
            float cvv = v; int cix = p;
            #pragma unroll
            for (int k=0;k<NPTS;k++){
                bool better = (cvv > lv[k]) || (cvv == lv[k] && cix < li[k]);
                float tv = lv[k]; int ti = li[k];
                if (better){ lv[k] = cvv; li[k] = cix; cvv = tv; cix = ti; }
            }
        }
        int ptr = 0;
        for (int r = 0; r < NPTS; r++){
            unsigned long long mykey = 0ULL;
            if (ptr < NPTS && lv[ptr] > -1e29f)
                mykey = ((unsigned long long)__float_as_uint(lv[ptr]) << 32)
                      | (unsigned int)(~(unsigned)li[ptr]);
            bestkey[tid] = mykey;
            __syncthreads();
            for (int st = 512; st > 0; st >>= 1){
                if (tid < st){
                    unsigned long long o = bestkey[tid+st];
                    if (o > bestkey[tid]) bestkey[tid] = o;
                }
                __syncthreads();
            }
            unsigned long long win = bestkey[0];
            if (tid == 0){ fbIdx[r] = (int)(~(unsigned)(win & 0xffffffffu)); sWin = win; }
            __syncthreads();
            if (mykey != 0ULL && mykey == sWin) ptr++;
            __syncthreads();
        }
    }

    if (tid < NPTS){
        int si = (tid < cnt) ? chosenIdx[tid] : fbIdx[tid - cnt];
        out[b*20 + tid*2 + 0] = (float)(si & (HS-1)) * (1.0f/512.0f);
        out[b*20 + tid*2 + 1] = (float)(si >> 9)     * (1.0f/512.0f);
        out[BATCH*NPTS*2 + b*NPTS + tid] = 1.0f;
    }
}

// ---------------- launch ----------------
extern "C" void kernel_launch(void* const* d_in, const int* in_sizes, int n_in,
                              void* d_out, int out_size){
    (void)in_sizes; (void)n_in; (void)out_size;
    const float* rgb = (const float*)d_in[0];
    const float* dep = (const float*)d_in[1];
    const float* w1  = (const float*)d_in[2];
    const float* b1  = (const float*)d_in[3];
    const float* gam = (const float*)d_in[4];
    const float* bet = (const float*)d_in[5];
    const float* mu  = (const float*)d_in[6];
    const float* var = (const float*)d_in[7];
    const float* w2  = (const float*)d_in[8];
    const float* b2  = (const float*)d_in[9];
    float* out = (float*)d_out;
    float* masks = out + (BATCH*NPTS*2 + BATCH*NPTS + BATCH*4);  // 272

    dim3 blk(32,8);
    // stage reordered weights into constant bank (d2d async copy: graph-capturable)
    kw_reorder<<<14, 256>>>(w1);
    void* wsrc = nullptr;
    cudaGetSymbolAddress(&wsrc, g_wre);
    cudaMemcpyToSymbolAsync(cW, wsrc, 3456*sizeof(float), 0, cudaMemcpyDeviceToDevice, 0);

    k1_freq<<<dim3(16,64,BATCH), blk>>>(rgb, dep);
    k2_smooth<<<dim3(16,64,BATCH*2), blk>>>();
    k3_conv<<<dim3(16,32,BATCH), 256>>>(b1,gam,bet,mu,var,w2,b2);
    k45_mask_peaks<<<dim3(16,64,BATCH), blk>>>(masks);
    cudaFuncSetAttribute(k6_points, cudaFuncAttributeMaxDynamicSharedMemorySize, 86528);
    k6_points<<<2*BATCH, 1024, 86528>>>(out);
}

// round 10
// speedup vs baseline: 4.8695x; 1.0573x over previous
#include <cuda_runtime.h>
#include <math.h>

#define BATCH 8
#define HW 1024
#define HS 512
#define NPIX (HS*HS)
#define NPTS 10
#define KP 512
#define SORTN 8192
#define ER 22
#define EC 38

// ---------------- scratch (device globals; no allocation) ----------------
__device__ float g_sal[BATCH*NPIX];
__device__ float g_cand_val[BATCH*NPIX];
__device__ int   g_cand_idx[BATCH*NPIX];
__device__ int   g_cand_cnt[BATCH];
__device__ int   g_rowflag[BATCH*HW];
__device__ int   g_colflag[BATCH*HW];

// reordered conv1 weights: [(c*9+tap)*8 + q] = ulonglong2{oc 4q..4q+1, oc 4q+2..4q+3}
__device__ __align__(16) float g_wre[3456];
__constant__ __align__(16) ulonglong2 cW[864];

// ---------------- packed f32x2 helpers ----------------
__device__ __forceinline__ unsigned long long fma2(unsigned long long a,
                                                   unsigned long long b,
                                                   unsigned long long c){
    unsigned long long d;
    asm("fma.rn.f32x2 %0, %1, %2, %3;" : "=l"(d) : "l"(a), "l"(b), "l"(c));
    return d;
}
__device__ __forceinline__ unsigned long long pack2(float v){
    unsigned long long d;
    asm("mov.b64 %0, {%1, %1};" : "=l"(d) : "f"(v));
    return d;
}
__device__ __forceinline__ void unpack2(unsigned long long p, float& lo, float& hi){
    asm("mov.b64 {%0, %1}, %2;" : "=f"(lo), "=f"(hi) : "l"(p));
}

// ---------------- KW: reorder conv1 weights + zero flags/counters ----------------
__global__ void kw_reorder(const float* __restrict__ w1){
    int l = blockIdx.x*256 + threadIdx.x;
    if (l < 3456){
        int tl = l >> 5, oc = l & 31;
        g_wre[tl*32 + oc] = w1[oc*108 + tl];
    }
    if (l < BATCH*HW){ g_rowflag[l] = 0; g_colflag[l] = 0; }
    if (l < BATCH) g_cand_cnt[l] = 0;
}

// ---------------- K3: fused DWT+energy+smooth+conv+BN+GELU+conv1x1+sigmoid ----------------
__global__ __launch_bounds__(256, 1) void k3_conv(
    const float* __restrict__ rgb, const float* __restrict__ dep,
    const float* __restrict__ b1,
    const float* __restrict__ gam, const float* __restrict__ bet,
    const float* __restrict__ mu,  const float* __restrict__ var,
    const float* __restrict__ w2,  const float* __restrict__ b2)
{
    __shared__ float sIn[12*18*34];          // 12 ch x (18 rows x 34 cols), halo 1
    __shared__ float sE[2*ER*EC];            // E_rgb, E_dep on 22x38 (halo 3)
    __shared__ float sH[2*ER*34];            // horizontally smoothed E
    __shared__ float sSc[32], sSh[32], sW2[32];
    __shared__ float sB2;
    int tid = threadIdx.x;
    int b = blockIdx.z;
    int ty0 = blockIdx.y*16, tx0 = blockIdx.x*32;

    // normalized separable gaussian (identical to former k2)
    const float e0 = 1.0f, e1 = 0.60653065971f, e2 = 0.13533528323f;
    const float sum1 = e0 + 2.f*e1 + 2.f*e2;
    const float w0 = e0/sum1, w1c = e1/sum1, w2c = e2/sum1;

    size_t plane = (size_t)HW*HW;
    const float* RP = rgb + (size_t)b*3*plane;
    const float* GP = RP + plane;
    const float* BP = GP + plane;
    const float* DP = dep + (size_t)b*plane;

    // ---- phase A: gray + Haar DWT + energy on the 22x38 halo region ----
    for (int l = tid; l < ER*EC; l += 256){
        int ey = l / EC, ex = l - ey*EC;
        int gy = ty0 - 3 + ey, gx = tx0 - 3 + ex;
        bool in = (gy >= 0 && gy < HS && gx >= 0 && gx < HS);
        float er = 0.f, ed = 0.f;
        float LLr=0.f,LHr=0.f,HLr=0.f,HHr=0.f, LLd=0.f,LHd=0.f,HLd=0.f,HHd=0.f;
        if (in){
            int i00 = (2*gy)*HW + 2*gx;
            int i01 = i00 + 1, i10 = i00 + HW, i11 = i00 + HW + 1;
            float v00 = (RP[i00]+GP[i00]+BP[i00])/3.0f;
            float v01 = (RP[i01]+GP[i01]+BP[i01])/3.0f;
            float v10 = (RP[i10]+GP[i10]+BP[i10])/3.0f;
            float v11 = (RP[i11]+GP[i11]+BP[i11])/3.0f;
            {
                float a=v00*0.5f, c2=v10*0.5f, e22=v01*0.5f, f2=v11*0.5f;
                LLr=a+c2; LHr=a-c2; HLr=e22+f2; HHr=e22-f2;
                er = sqrtf(LHr*LHr+HLr*HLr+HHr*HHr+1e-8f);
            }
            {
                float a=DP[i00]*0.5f, c2=DP[i10]*0.5f, e22=DP[i01]*0.5f, f2=DP[i11]*0.5f;
                LLd=a+c2; LHd=a-c2; HLd=e22+f2; HHd=e22-f2;
                ed = sqrtf(LHd*LHd+HLd*HLd+HHd*HHd+1e-8f);
            }
        }
        sE[l] = er; sE[ER*EC + l] = ed;
        int iy = ey - 2, ix = ex - 2;
        if (iy >= 0 && iy < 18 && ix >= 0 && ix < 34){
            int o = iy*34 + ix;
            sIn[0*612+o]=LLr; sIn[1*612+o]=LHr; sIn[2*612+o]=HLr; sIn[3*612+o]=HHr;
            sIn[4*612+o]=LLd; sIn[5*612+o]=LHd; sIn[6*612+o]=HLd; sIn[7*612+o]=HHd;
            sIn[8*612+o]=er;  sIn[9*612+o]=ed;
        }
    }
    if (tid < 32){
        float inv = 1.0f/sqrtf(var[tid] + 1e-5f);
        float sc = gam[tid]*inv;
        sSc[tid] = sc;
        sSh[tid] = (b1[tid] - mu[tid])*sc + bet[tid];
        sW2[tid] = w2[tid];
    }
    if (tid == 0) sB2 = b2[0];
    __syncthreads();

    // ---- phase B: horizontal smooth (identical formula to former k2) ----
    for (int l = tid; l < 2*ER*34; l += 256){
        int ch = l / (ER*34);
        int rr = l - ch*(ER*34);
        int r = rr/34, c = rr - r*34;
        const float* e = sE + ch*ER*EC + r*EC + c;
        sH[l] = w2c*(e[0]+e[4]) + w1c*(e[1]+e[3]) + w0*e[2];
    }
    __syncthreads();

    // ---- phase C: vertical smooth -> channels 10, 11 (ZERO outside image: conv pad) ----
    for (int l = tid; l < 2*612; l += 256){
        int ch = l / 612;
        int o = l - ch*612;
        int iy = o/34, ix = o - iy*34;
        int gy = ty0 + iy - 1, gx = tx0 + ix - 1;          // image coords of this sIn cell
        float v = 0.f;
        if (gy >= 0 && gy < HS && gx >= 0 && gx < HS){     // conv1 zero-padding
            const float* h = sH + ch*(ER*34) + iy*34 + ix;
            v = w2c*(h[0]+h[4*34]) + w1c*(h[1*34]+h[3*34]) + w0*h[2*34];
        }
        sIn[(10+ch)*612 + o] = v;
    }
    __syncthreads();

    // ---- mainloop: conv3x3(12->32), f32x2, weights in constant bank ----
    int ty = tid >> 5, tx = tid & 31;
    unsigned long long accA[16], accB[16];
    #pragma unroll
    for (int i=0;i<16;i++){ accA[i] = 0ULL; accB[i] = 0ULL; }
    for (int c=0; c<12; c++){
        #pragma unroll
        for (int tap=0; tap<9; tap++){
            int ky = tap/3, kx = tap%3;
            float a0 = sIn[c*612 + (ty+ky)*34 + (tx+kx)];
            float a1 = sIn[c*612 + (ty+8+ky)*34 + (tx+kx)];
            unsigned long long v0 = pack2(a0), v1 = pack2(a1);
            const ulonglong2* wrow = cW + (c*9+tap)*8;
            #pragma unroll
            for (int q=0;q<8;q++){
                ulonglong2 wp = wrow[q];
                accA[2*q+0] = fma2(v0, wp.x, accA[2*q+0]);
                accA[2*q+1] = fma2(v0, wp.y, accA[2*q+1]);
                accB[2*q+0] = fma2(v1, wp.x, accB[2*q+0]);
                accB[2*q+1] = fma2(v1, wp.y, accB[2*q+1]);
            }
        }
    }
    float zA = sB2, zB = sB2;
    #pragma unroll
    for (int j=0; j<16; j++){
        float a0, a1, b0, b1v;
        unpack2(accA[j], a0, a1);
        unpack2(accB[j], b0, b1v);
        int oc = 2*j;
        {
            float xv = fmaf(a0, sSc[oc], sSh[oc]);
            float gl = 0.5f*xv*(1.0f + tanhf(0.7978845608f*(xv + 0.044715f*xv*xv*xv)));
            zA = fmaf(gl, sW2[oc], zA);
        }
        {
            float xv = fmaf(a1, sSc[oc+1], sSh[oc+1]);
            float gl = 0.5f*xv*(1.0f + tanhf(0.7978845608f*(xv + 0.044715f*xv*xv*xv)));
            zA = fmaf(gl, sW2[oc+1], zA);
        }
        {
            float xv = fmaf(b0, sSc[oc], sSh[oc]);
            float gl = 0.5f*xv*(1.0f + tanhf(0.7978845608f*(xv + 0.044715f*xv*xv*xv)));
            zB = fmaf(gl, sW2[oc], zB);
        }
        {
            float xv = fmaf(b1v, sSc[oc+1], sSh[oc+1]);
            float gl = 0.5f*xv*(1.0f + tanhf(0.7978845608f*(xv + 0.044715f*xv*xv*xv)));
            zB = fmaf(gl, sW2[oc+1], zB);
        }
    }
    float* S = g_sal + (size_t)b*NPIX;
    S[(ty0+ty)*HS + (tx0+tx)]     = 1.0f/(1.0f + expf(-zA));
    S[(ty0+ty+8)*HS + (tx0+tx)]   = 1.0f/(1.0f + expf(-zB));
}

// ---------------- K45: fused bilinear x2 upsample + flags + peaks ----------------
__global__ void k45_mask_peaks(float* __restrict__ masks){
    __shared__ int colAny[64];
    __shared__ int rowAny[16];
    __shared__ float sv[256];
    __shared__ int   si[256];
    __shared__ int   scnt, sbase;
    int tx = threadIdx.x, ty = threadIdx.y;
    int tid = ty*32 + tx;
    if (tid < 64) colAny[tid] = 0;
    if (tid < 16) rowAny[tid] = 0;
    if (tid == 0) scnt = 0;
    __syncthreads();
    int x = blockIdx.x*32 + tx;
    int y = blockIdx.y*8  + ty;
    int b = blockIdx.z;
    const float* s = g_sal + (size_t)b*NPIX;
    int xm = max(x-1,0), xp = min(x+1,HS-1);
    int ym = max(y-1,0), yp = min(y+1,HS-1);
    float n00=s[ym*HS+xm], n01=s[ym*HS+x], n02=s[ym*HS+xp];
    float n10=s[y*HS+xm],  v  =s[y*HS+x],  n12=s[y*HS+xp];
    float n20=s[yp*HS+xm], n21=s[yp*HS+x], n22=s[yp*HS+xp];
    float mp = fmaxf(fmaxf(fmaxf(n00,n01),fmaxf(n02,n10)),
                     fmaxf(fmaxf(v,n12),fmaxf(fmaxf(n20,n21),n22)));
    bool pk = (v == mp) && (v > 0.f);
    if (pk){
        int p = atomicAdd(&scnt, 1);
        sv[p] = v; si[p] = y*HS + x;
    }
    float m00 = 0.25f*(0.25f*n00 + 0.75f*n01) + 0.75f*(0.25f*n10 + 0.75f*v);
    float m01 = 0.25f*(0.75f*n01 + 0.25f*n02) + 0.75f*(0.75f*v + 0.25f*n12);
    float m10 = 0.75f*(0.25f*n10 + 0.75f*v)   + 0.25f*(0.25f*n20 + 0.75f*n21);
    float m11 = 0.75f*(0.75f*v + 0.25f*n12)   + 0.25f*(0.75f*n21 + 0.25f*n22);
    float* M = masks + (size_t)b*HW*HW;
    *(float2*)&M[(size_t)(2*y)*HW   + 2*x] = make_float2(m00, m01);
    *(float2*)&M[(size_t)(2*y+1)*HW + 2*x] = make_float2(m10, m11);
    bool r0 = (m00 > 0.5f) || (m01 > 0.5f);
    bool r1 = (m10 > 0.5f) || (m11 > 0.5f);
    bool c0 = (m00 > 0.5f) || (m10 > 0.5f);
    bool c1 = (m01 > 0.5f) || (m11 > 0.5f);
    if (r0) rowAny[2*ty] = 1;
    if (r1) rowAny[2*ty+1] = 1;
    if (c0) colAny[2*tx] = 1;
    if (c1) colAny[2*tx+1] = 1;
    __syncthreads();
    if (tid < 16 && rowAny[tid]) atomicOr(&g_rowflag[b*HW + blockIdx.y*16 + tid], 1);
    if (tid < 64 && colAny[tid]) atomicOr(&g_colflag[b*HW + blockIdx.x*64 + tid], 1);
    if (tid == 0 && scnt) sbase = atomicAdd(&g_cand_cnt[b], scnt);
    __syncthreads();
    if (tid < scnt){
        g_cand_val[(size_t)b*NPIX + sbase + tid] = sv[tid];
        g_cand_idx[(size_t)b*NPIX + sbase + tid] = si[tid];
    }
}

// ---------------- K6: points (blocks 0..7) + boxes (blocks 8..15) ----------------
__global__ __launch_bounds__(1024) void k6_points(float* __restrict__ out){
    extern __shared__ unsigned char sraw[];
    int tid = threadIdx.x;

    if (blockIdx.x >= BATCH){
        int b = blockIdx.x - BATCH;
        int* sred = (int*)sraw;
        int rf = g_rowflag[b*HW + tid];
        int cf = g_colflag[b*HW + tid];
        int res[4];
        int init[4] = { rf ? tid : HW, rf ? tid : -1, cf ? tid : HW, cf ? tid : -1 };
        #pragma unroll
        for (int w = 0; w < 4; w++){
            sred[tid] = init[w];
            __syncthreads();
            for (int st = 512; st > 0; st >>= 1){
                if (tid < st){
                    int o = sred[tid+st];
                    sred[tid] = (w == 0 || w == 2) ? min(sred[tid], o) : max(sred[tid], o);
                }
                __syncthreads();
            }
            res[w] = sred[0];
            __syncthreads();
        }
        if (tid == 0){
            float* bx = out + BATCH*NPTS*2 + BATCH*NPTS + b*4;
            if (res[1] >= 0){ bx[0]=(float)res[2]; bx[1]=(float)res[0]; bx[2]=(float)res[3]; bx[3]=(float)res[1]; }
            else            { bx[0]=0.f; bx[1]=0.f; bx[2]=(float)(HW-1); bx[3]=(float)(HW-1); }
        }
        return;
    }

    unsigned long long* keys = (unsigned long long*)sraw;
    unsigned int* hist = (unsigned int*)(sraw + 65536);
    unsigned long long* bestkey = (unsigned long long*)(sraw + 65536);
    int* part = (int*)(sraw + 81920);
    unsigned char* avail = (unsigned char*)(sraw + 86016);
    __shared__ int s_ti[KP];
    __shared__ int sT, sTf, sM, sChi, sCnt, sPick, sCur;
    __shared__ int chosenIdx[NPTS];
    __shared__ int fbIdx[NPTS];
    __shared__ unsigned long long sWin;

    int b = blockIdx.x;
    int N = g_cand_cnt[b];
    if (N > NPIX) N = NPIX;
    int need = min(KP, N);
    const float* cv = g_cand_val + (size_t)b*NPIX;
    const int*   ci = g_cand_idx + (size_t)b*NPIX;

    hist[tid] = 0u; hist[tid+1024] = 0u; hist[tid+2048] = 0u; hist[tid+3072] = 0u;
    if (tid == 0){ sT = 0; sM = 0; sChi = 0; sTf = 0; }
    __syncthreads();
    for (int i = tid; i < N; i += 1024){
        int bin = max(0, min(4095, (int)(cv[i]*4096.0f)));
        atomicAdd(&hist[bin], 1u);
    }
    __syncthreads();
    int t4 = tid*4;
    {
        int h0 = hist[t4], h1 = hist[t4+1], h2 = hist[t4+2], h3 = hist[t4+3];
        part[tid] = h0+h1+h2+h3;
        __syncthreads();
        for (int d = 1; d < 1024; d <<= 1){
            int v = (tid + d < 1024) ? part[tid + d] : 0;
            __syncthreads();
            part[tid] += v;
            __syncthreads();
        }
        int base = part[tid];
        int s1 = base - h0, s2 = s1 - h1, s3 = s2 - h2;
        int bestT = -1;
        if (s3 >= need) bestT = t4+3;
        else if (s2 >= need) bestT = t4+2;
        else if (s1 >= need) bestT = t4+1;
        else if (base >= need) bestT = t4;
        if (bestT >= 0) atomicMax(&sT, bestT);
    }
    __syncthreads();
    int T = sT;
    hist[tid] = 0u; hist[tid+1024] = 0u; hist[tid+2048] = 0u; hist[tid+3072] = 0u;
    __syncthreads();
    for (int i = tid; i < N; i += 1024){
        float v = cv[i];
        int bin = max(0, min(4095, (int)(v*4096.0f)));
        if (bin > T) atomicAdd(&sChi, 1);
        else if (bin == T){
            float frac = v*4096.0f - (float)T;
            int fb = max(0, min(4095, (int)(frac*4096.0f)));
            atomicAdd(&hist[fb], 1u);
        }
    }
    __syncthreads();
    int needF = need - sChi;
    {
        int h0 = hist[t4], h1 = hist[t4+1], h2 = hist[t4+2], h3 = hist[t4+3];
        part[tid] = h0+h1+h2+h3;
        __syncthreads();
        for (int d = 1; d < 1024; d <<= 1){
            int v = (tid + d < 1024) ? part[tid + d] : 0;
            __syncthreads();
            part[tid] += v;
            __syncthreads();
        }
        int base = part[tid];
        int s1 = base - h0, s2 = s1 - h1, s3 = s2 - h2;
        int bestT = -1;
        if (s3 >= needF) bestT = t4+3;
        else if (s2 >= needF) bestT = t4+2;
        else if (s1 >= needF) bestT = t4+1;
        else if (base >= needF) bestT = t4;
        if (bestT >= 0) atomicMax(&sTf, bestT);
    }
    __syncthreads();
    int Tf = sTf;
    for (int i = tid; i < N; i += 1024){
        float v = cv[i];
        int bin = max(0, min(4095, (int)(v*4096.0f)));
        bool take = (bin > T);
        if (!take && bin == T){
            float frac = v*4096.0f - (float)T;
            int fb = max(0, min(4095, (int)(frac*4096.0f)));
            take = (fb >= Tf);
        }
        if (take){
            int p = atomicAdd(&sM, 1);
            if (p < SORTN)
                keys[p] = ((unsigned long long)__float_as_uint(v) << 32)
                        | (unsigned int)(~(unsigned)ci[i]);
        }
    }
    __syncthreads();
    int M = min(sM, SORTN);
    int S = 512;
    while (S < M) S <<= 1;
    for (int i = M + tid; i < S; i += 1024) keys[i] = 0ULL;
    __syncthreads();
    for (int k = 2; k <= S; k <<= 1){
        for (int j = k >> 1; j > 0; j >>= 1){
            for (int i = tid; i < S; i += 1024){
                int ixj = i ^ j;
                if (ixj > i){
                    unsigned long long a = keys[i], c = keys[ixj];
                    bool up = ((i & k) == 0);
                    if ((a > c) == up){ keys[i] = c; keys[ixj] = a; }
                }
            }
            __syncthreads();
        }
    }
    if (tid < KP){
        s_ti[tid] = (int)(~(unsigned)(keys[S-1-tid] & 0xffffffffu));
        avail[tid] = 1;
    }
    __syncthreads();

    int Kv = min(N, KP);
    if (tid == 0){ sCnt = 0; sCur = 0; }
    __syncthreads();
    for (int round = 0; round < NPTS; round++){
        if (tid == 0){
            int i = sCur;
            while (i < Kv && !avail[i]) i++;
            if (i < Kv){
                chosenIdx[sCnt] = s_ti[i];
                sCnt++;
                sPick = i;
                sCur = i + 1;
            } else sPick = -1;
        }
        __syncthreads();
        int i = sPick;
        if (i < 0) break;
        int idx = s_ti[i];
        int xi = idx & (HS-1), yi = idx >> 9;
        if (tid < KP && tid > i && tid < Kv && avail[tid]){
            int dx = (s_ti[tid] & (HS-1)) - xi;
            int dy = (s_ti[tid] >> 9) - yi;
            if (dx*dx + dy*dy < 625) avail[tid] = 0;
        }
        __syncthreads();
    }
    int cnt = sCnt;

    if (cnt < NPTS){
        const float* s = g_sal + (size_t)b*NPIX;
        float lv[NPTS]; int li[NPTS];
        #pragma unroll
        for (int k=0;k<NPTS;k++){ lv[k] = -1e30f; li[k] = 0x7fffffff; }
        for (int p = tid; p < NPIX; p += 1024){
            float v = s[p];
            if (v <= lv[NPTS-1]) continue;
            int y = p >> 9, x = p & (HS-1);
            float mp = v;
            #pragma unroll
            for (int dy=-1; dy<=1; dy++){
                int yy = y + dy; if (yy < 0 || yy >= HS) continue;
                #pragma unroll
                for (int dx=-1; dx<=1; dx++){
                    int xx = x + dx; if (xx < 0 || xx >= HS) continue;
                    mp = fmaxf(mp, s[yy*HS + xx]);
                }
            }
            if (v == mp) continue;
            float cvv = v; int cix = p;
            #pragma unroll
            for (int k=0;k<NPTS;k++){
                bool better = (cvv > lv[k]) || (cvv == lv[k] && cix < li[k]);
                float tv = lv[k]; int ti = li[k];
                if (better){ lv[k] = cvv; li[k] = cix; cvv = tv; cix = ti; }
            }
        }
        int ptr = 0;
        for (int r = 0; r < NPTS; r++){
            unsigned long long mykey = 0ULL;
            if (ptr < NPTS && lv[ptr] > -1e29f)
                mykey = ((unsigned long long)__float_as_uint(lv[ptr]) << 32)
                      | (unsigned int)(~(unsigned)li[ptr]);
            bestkey[tid] = mykey;
            __syncthreads();
            for (int st = 512; st > 0; st >>= 1){
                if (tid < st){
                    unsigned long long o = bestkey[tid+st];
                    if (o > bestkey[tid]) bestkey[tid] = o;
                }
                __syncthreads();
            }
            unsigned long long win = bestkey[0];
            if (tid == 0){ fbIdx[r] = (int)(~(unsigned)(win & 0xffffffffu)); sWin = win; }
            __syncthreads();
            if (mykey != 0ULL && mykey == sWin) ptr++;
            __syncthreads();
        }
    }

    if (tid < NPTS){
        int si = (tid < cnt) ? chosenIdx[tid] : fbIdx[tid - cnt];
        out[b*20 + tid*2 + 0] = (float)(si & (HS-1)) * (1.0f/512.0f);
        out[b*20 + tid*2 + 1] = (float)(si >> 9)     * (1.0f/512.0f);
        out[BATCH*NPTS*2 + b*NPTS + tid] = 1.0f;
    }
}

// ---------------- launch ----------------
extern "C" void kernel_launch(void* const* d_in, const int* in_sizes, int n_in,
                              void* d_out, int out_size){
    (void)in_sizes; (void)n_in; (void)out_size;
    const float* rgb = (const float*)d_in[0];
    const float* dep = (const float*)d_in[1];
    const float* w1  = (const float*)d_in[2];
    const float* b1  = (const float*)d_in[3];
    const float* gam = (const float*)d_in[4];
    const float* bet = (const float*)d_in[5];
    const float* mu  = (const float*)d_in[6];
    const float* var = (const float*)d_in[7];
    const float* w2  = (const float*)d_in[8];
    const float* b2  = (const float*)d_in[9];
    float* out = (float*)d_out;
    float* masks = out + (BATCH*NPTS*2 + BATCH*NPTS + BATCH*4);  // 272

    dim3 blk(32,8);
    kw_reorder<<<32, 256>>>(w1);
    void* wsrc = nullptr;
    cudaGetSymbolAddress(&wsrc, g_wre);
    cudaMemcpyToSymbolAsync(cW, wsrc, 3456*sizeof(float), 0, cudaMemcpyDeviceToDevice, 0);

    k3_conv<<<dim3(16,32,BATCH), 256>>>(rgb,dep,b1,gam,bet,mu,var,w2,b2);
    k45_mask_peaks<<<dim3(16,64,BATCH), blk>>>(masks);
    cudaFuncSetAttribute(k6_points, cudaFuncAttributeMaxDynamicSharedMemorySize, 86528);
    k6_points<<<2*BATCH, 1024, 86528>>>(out);
}